// round 13
// baseline (speedup 1.0000x reference)
#include <cuda_runtime.h>
#include <cuda_bf16.h>
#include <cstdint>

#define Bsz 8
#define Ssz 1024
#define Esz 768
#define Hsz 12
#define Dsz 64
#define Msz (Bsz*Ssz)   // 8192

// ---------------- scratch (device globals; referenced ONLY in device code) ----------------
__device__ float g_q[Bsz*Hsz*Ssz*Dsz];     // rounded + 0.125-scaled q
__device__ float g_k[Bsz*Hsz*Ssz*Dsz];     // rounded k
__device__ float g_v[Bsz*Hsz*Ssz*Dsz];     // rounded v
__device__ float g_attn[Bsz*Ssz*Esz];      // rounded attention output
__device__ float g_xr[(size_t)Msz*Esz];    // rounded X
__device__ float g_wT[(size_t)(3*Esz)*Esz];// rounded W^T [2304][768], q rows pre-scaled
__device__ float g_woT[(size_t)Esz*Esz];   // rounded Wo^T [768][768]

// ---------------- helpers ----------------
__device__ __forceinline__ unsigned f2tf(float f) {
    unsigned u;
    asm("cvt.rna.tf32.f32 %0, %1;" : "=r"(u) : "f"(f));
    return u;
}
__device__ __forceinline__ float roundtf(float f) { return __uint_as_float(f2tf(f)); }
__device__ __forceinline__ void mma_tf32(float* c, const unsigned* a, unsigned b0, unsigned b1) {
    asm volatile(
        "mma.sync.aligned.m16n8k8.row.col.f32.tf32.tf32.f32 "
        "{%0,%1,%2,%3}, {%4,%5,%6,%7}, {%8,%9}, {%0,%1,%2,%3};"
        : "+f"(c[0]), "+f"(c[1]), "+f"(c[2]), "+f"(c[3])
        : "r"(a[0]), "r"(a[1]), "r"(a[2]), "r"(a[3]), "r"(b0), "r"(b1));
}
__device__ __forceinline__ void ldsm_x4(unsigned& r0, unsigned& r1, unsigned& r2, unsigned& r3,
                                        unsigned saddr) {
    asm volatile("ldmatrix.sync.aligned.m8n8.x4.shared.b16 {%0,%1,%2,%3}, [%4];"
        : "=r"(r0), "=r"(r1), "=r"(r2), "=r"(r3) : "r"(saddr));
}
__device__ __forceinline__ unsigned smem_u32(const void* p) {
    unsigned a;
    asm("{ .reg .u64 t; cvta.to.shared.u64 t, %1; cvt.u32.u64 %0, t; }" : "=r"(a) : "l"(p));
    return a;
}
__device__ __forceinline__ void cp16(unsigned dst, const float* src) {
    asm volatile("cp.async.cg.shared.global [%0], [%1], 16;" :: "r"(dst), "l"(src));
}
#define CP_COMMIT()  asm volatile("cp.async.commit_group;" ::: "memory")
#define CP_WAIT1()   asm volatile("cp.async.wait_group 1;" ::: "memory")

// ============================================================================
// Conversion kernels (one-time, tiny). Write device globals from device code.
// ============================================================================
__global__ __launch_bounds__(256) void conv_round(const float* __restrict__ src)
{
    int i = (blockIdx.x * 256 + threadIdx.x) * 4;
    float4 v = *(const float4*)(src + i);
    v.x = roundtf(v.x); v.y = roundtf(v.y); v.z = roundtf(v.z); v.w = roundtf(v.w);
    *(float4*)(g_xr + i) = v;
}

__global__ __launch_bounds__(128) void conv_wqkvT(const float* __restrict__ Wq,
                                                  const float* __restrict__ Wk,
                                                  const float* __restrict__ Wv)
{
    int n = blockIdx.x;
    int which = n / Esz, rem = n % Esz, h = rem >> 6, d = rem & 63;
    const float* W = (which == 0) ? Wq : (which == 1 ? Wk : Wv);
    const float sc = (which == 0) ? 0.125f : 1.0f;
    const float* col = W + (size_t)h * Esz * Dsz + d;
    float* row = g_wT + (size_t)n * Esz;
    for (int e = threadIdx.x; e < Esz; e += 128)
        row[e] = roundtf(col[(size_t)e * Dsz] * sc);
}

__global__ __launch_bounds__(128) void conv_woT(const float* __restrict__ Wo)
{
    int n = blockIdx.x;
    float* row = g_woT + (size_t)n * Esz;
    for (int e = threadIdx.x; e < Esz; e += 128)
        row[e] = roundtf(Wo[(size_t)e * Esz + n]);
}

// ============================================================================
// tf32 GEMM, 3-stage cp.async pipeline, Kc=32 — UNCHANGED from R12 (proven).
// ============================================================================
#define AST 36
#define BKST 36
#define STG_WORDS (128*AST + 128*BKST)   // 9216
#define STG_BYTES (STG_WORDS*4)          // 36864
#define GSMEM (3*STG_BYTES)              // 110592
#define AOFF  (128*AST*4)
#define CHUNKS 24

__global__ __launch_bounds__(256, 2) void gemm_ca(
    const float* __restrict__ b0p, const float* __restrict__ b1p,
    const float* __restrict__ b2p,
    float* __restrict__ Out, int mode)
{
    extern __shared__ __align__(16) unsigned smem[];
    const unsigned sbase = smem_u32(smem);

    const float* A  = (mode == 0) ? g_xr : g_attn;
    const float* Bt = (mode == 0) ? g_wT : g_woT;

    const int t    = threadIdx.x;
    const int warp = t >> 5;
    const int lane = t & 31;
    const int g    = lane >> 2;
    const int tg   = lane & 3;
    const int wm   = (warp & 1) * 64;
    const int wn   = (warp >> 1) * 32;
    const int n0   = blockIdx.x * 128;
    const int m0   = blockIdx.y * 128;

    const unsigned a_lane = (((lane >> 3) & 1) * 8 + (lane & 7)) * AST + (lane >> 4) * 4;
    const unsigned b_lane = (lane & 7) * BKST + (lane >> 3) * 4;

    const int row_ = t >> 3;
    const int seg_ = t & 7;
    const float* AgBase = A  + (size_t)m0 * Esz + seg_ * 4;
    const float* BgBase = Bt + (size_t)n0 * Esz + seg_ * 4;

#define GISSUE(chunk, buf) do {                                               \
    const unsigned s0 = sbase + (unsigned)(buf) * STG_BYTES;                  \
    const int c0 = (chunk) * 32;                                              \
    _Pragma("unroll")                                                         \
    for (int it = 0; it < 4; it++) {                                          \
        const int row = row_ + it * 32;                                       \
        cp16(s0 + (unsigned)(row * AST + seg_ * 4) * 4,                       \
             AgBase + (size_t)row * Esz + c0);                                \
        cp16(s0 + AOFF + (unsigned)(row * BKST + seg_ * 4) * 4,               \
             BgBase + (size_t)row * Esz + c0);                                \
    }                                                                         \
} while (0)

    GISSUE(0, 0); CP_COMMIT();
    GISSUE(1, 1); CP_COMMIT();

    float acc[4][4][4];
    #pragma unroll
    for (int mi = 0; mi < 4; mi++)
        #pragma unroll
        for (int ni = 0; ni < 4; ni++)
            #pragma unroll
            for (int j = 0; j < 4; j++) acc[mi][ni][j] = 0.f;

    int buf = 0, buf2 = 2;
    for (int i = 0; i < CHUNKS; i++) {
        CP_WAIT1();
        __syncthreads();
        if (i + 2 < CHUNKS) GISSUE(i + 2, buf2);
        CP_COMMIT();

        const unsigned sA = sbase + (unsigned)buf * STG_BYTES;
        const unsigned sB = sA + AOFF;

        #pragma unroll
        for (int ksp = 0; ksp < 2; ksp++) {
            unsigned bf[4][4];
            #pragma unroll
            for (int ni = 0; ni < 4; ni++)
                ldsm_x4(bf[ni][0], bf[ni][1], bf[ni][2], bf[ni][3],
                        sB + 4 * ((wn + ni * 8) * BKST + ksp * 16 + b_lane));
            #pragma unroll
            for (int ks2 = 0; ks2 < 2; ks2++) {
                const int ks = ksp * 2 + ks2;
                unsigned a[4][4];
                #pragma unroll
                for (int mi = 0; mi < 4; mi++)
                    ldsm_x4(a[mi][0], a[mi][1], a[mi][2], a[mi][3],
                            sA + 4 * ((wm + mi * 16) * AST + ks * 8 + a_lane));
                #pragma unroll
                for (int ni = 0; ni < 4; ni++)
                    #pragma unroll
                    for (int mi = 0; mi < 4; mi++)
                        mma_tf32(acc[mi][ni], a[mi], bf[ni][2 * ks2], bf[ni][2 * ks2 + 1]);
            }
        }
        buf  = (buf  == 2) ? 0 : buf + 1;
        buf2 = (buf2 == 2) ? 0 : buf2 + 1;
    }
#undef GISSUE

    if (mode == 0) {
        const int which = n0 / Esz;
        const float* bias = (which == 0) ? b0p : (which == 1 ? b1p : b2p);
        float* OUTsel     = (which == 0) ? g_q : (which == 1 ? g_k : g_v);
        const float bsc   = (which == 0) ? 0.125f : 1.0f;
        const int nrel = n0 % Esz;
        #pragma unroll
        for (int mi = 0; mi < 4; mi++) {
            const int row_lo = m0 + wm + mi * 16 + g;
            const int row_hi = row_lo + 8;
            const int blo = row_lo >> 10, slo = row_lo & 1023;
            const int bhi = row_hi >> 10, shi = row_hi & 1023;
            #pragma unroll
            for (int ni = 0; ni < 4; ni++) {
                const int nc = nrel + wn + ni * 8 + 2 * tg;
                const int head = nc >> 6, d = nc & 63;
                float2 bb = *(const float2*)(bias + head * Dsz + d);
                bb.x *= bsc; bb.y *= bsc;
                float* olo = OUTsel + ((((size_t)blo * Hsz + head) << 10) + slo) * Dsz + d;
                float* ohi = OUTsel + ((((size_t)bhi * Hsz + head) << 10) + shi) * Dsz + d;
                float2 wlo, whi;
                wlo.x = roundtf(acc[mi][ni][0] + bb.x);
                wlo.y = roundtf(acc[mi][ni][1] + bb.y);
                whi.x = roundtf(acc[mi][ni][2] + bb.x);
                whi.y = roundtf(acc[mi][ni][3] + bb.y);
                *(float2*)olo = wlo;
                *(float2*)ohi = whi;
            }
        }
    } else {
        #pragma unroll
        for (int mi = 0; mi < 4; mi++) {
            const int row_lo = m0 + wm + mi * 16 + g;
            float* olo = Out + (size_t)row_lo * Esz + n0;
            float* ohi = olo + (size_t)8 * Esz;
            #pragma unroll
            for (int ni = 0; ni < 4; ni++) {
                const int col = wn + ni * 8 + 2 * tg;
                float2 bb = *(const float2*)(b0p + n0 + col);
                float2 wlo, whi;
                wlo.x = acc[mi][ni][0] + bb.x; wlo.y = acc[mi][ni][1] + bb.y;
                whi.x = acc[mi][ni][2] + bb.x; whi.y = acc[mi][ni][3] + bb.y;
                *(float2*)(olo + col) = wlo;
                *(float2*)(ohi + col) = whi;
            }
        }
    }
}

// ============================================================================
// Flash attention, Br=128, cp.async double-buffered K/V + separate P buffer.
// Layout (words): P[128][68] | K0[64][68] | K1 | V0[64][72] | V1  = 26624 w
// ============================================================================
#define KST 68
#define VST 72
#define P_WORDS   (128*KST)            // 8704
#define K_WORDS   (64*KST)             // 4352
#define V_WORDS   (64*VST)             // 4608
#define KOFF(b)   (P_WORDS + (b)*K_WORDS)
#define VOFF(b)   (P_WORDS + 2*K_WORDS + (b)*V_WORDS)
#define ATTN_SMEM ((P_WORDS + 2*K_WORDS + 2*V_WORDS)*4)   // 106496

__global__ __launch_bounds__(256) void attn_kernel()
{
    extern __shared__ __align__(16) unsigned asmem[];

    const int bh = blockIdx.y;
    const int b = bh / Hsz, h = bh % Hsz;
    const int tid  = threadIdx.x;
    const int warp = tid >> 5;
    const int lane = tid & 31;
    const int g  = lane >> 2;
    const int tg = lane & 3;
    const int r0 = warp * 16;

    const unsigned sbase   = smem_u32(asmem);
    const unsigned p_base  = sbase;                       // P buffer
    const unsigned kf_lane = (lane & 7) * KST + (lane >> 3) * 4;
    const unsigned pf_lane = (((lane >> 3) & 1) * 8 + (lane & 7)) * KST + (lane >> 4) * 4;

    // global tile bases (pre-rounded floats; raw copies)
    const float* Kg0 = g_k + (size_t)bh * (Ssz * Dsz);
    const float* Vg0 = g_v + (size_t)bh * (Ssz * Dsz);

    // cp.async mapping: 4 uint4 lines per thread per matrix per tile
    const int lrow = tid >> 4;             // 0..15 (16 rows per pass)
    const int lcol = (tid & 15) << 2;      // word col 0..60

#define AISSUE(kb, bsel) do {                                                  \
    const float* Kg = Kg0 + (size_t)(kb) * 64 * Dsz;                           \
    const float* Vg = Vg0 + (size_t)(kb) * 64 * Dsz;                           \
    const unsigned kd = sbase + KOFF(bsel) * 4;                                \
    const unsigned vd = sbase + VOFF(bsel) * 4;                                \
    _Pragma("unroll")                                                          \
    for (int it = 0; it < 4; it++) {                                           \
        const int row = lrow + it * 16;                                        \
        cp16(kd + (unsigned)(row * KST + lcol) * 4, Kg + row * Dsz + lcol);    \
        cp16(vd + (unsigned)(row * VST + lcol) * 4, Vg + row * Dsz + lcol);    \
    }                                                                          \
} while (0)

    // ---- stage Q (scaled+rounded) into P buffer, extract A-frags ----
    {
        const uint4* Qg = (const uint4*)(g_q + ((size_t)bh * Ssz + blockIdx.x * 128) * Dsz);
        unsigned* Psm = asmem;
        #pragma unroll
        for (int i = 0; i < 8; i++) {
            int idx = i * 256 + tid;
            int row = idx >> 4, c = (idx & 15) << 2;
            *(uint4*)&Psm[row * KST + c] = Qg[idx];
        }
    }
    // prologue: issue K/V tile 0 while staging Q
    AISSUE(0, 0); CP_COMMIT();
    __syncthreads();

    unsigned qa[8][4];
    #pragma unroll
    for (int kk = 0; kk < 8; kk++) {
        unsigned addr = p_base + 4 * (r0 * KST + kk * 8 + pf_lane);
        ldsm_x4(qa[kk][0], qa[kk][1], qa[kk][2], qa[kk][3], addr);
    }
    __syncthreads();                       // Q extracted; P buffer free for P

    float o[8][4];
    #pragma unroll
    for (int nf = 0; nf < 8; nf++)
        #pragma unroll
        for (int j = 0; j < 4; j++) o[nf][j] = 0.f;
    float m_lo = -1e30f, m_hi = -1e30f, l_lo = 0.f, l_hi = 0.f;

    for (int kb = 0; kb < Ssz / 64; kb++) {
        const int bsel = kb & 1;
        if (kb + 1 < Ssz / 64) AISSUE(kb + 1, bsel ^ 1);
        CP_COMMIT();
        CP_WAIT1();
        __syncthreads();                   // tile kb visible to all threads

        const unsigned k_base = sbase + KOFF(bsel) * 4;
        const unsigned* Vsm   = asmem + VOFF(bsel);

        // ---- S = Q K^T ----
        float s[8][4];
        #pragma unroll
        for (int nf = 0; nf < 8; nf++)
            #pragma unroll
            for (int j = 0; j < 4; j++) s[nf][j] = 0.f;

        #pragma unroll
        for (int nf = 0; nf < 8; nf++) {
            #pragma unroll
            for (int p = 0; p < 4; p++) {
                unsigned kb0, kb1, kb2, kb3;
                unsigned addr = k_base + 4 * ((nf * 8) * KST + p * 16 + kf_lane);
                ldsm_x4(kb0, kb1, kb2, kb3, addr);
                mma_tf32(s[nf], qa[2 * p],     kb0, kb1);
                mma_tf32(s[nf], qa[2 * p + 1], kb2, kb3);
            }
        }

        // ---- online softmax (P buffer is warp-private rows; no block sync) ----
        float tmax_lo = -1e30f, tmax_hi = -1e30f;
        #pragma unroll
        for (int nf = 0; nf < 8; nf++) {
            tmax_lo = fmaxf(tmax_lo, fmaxf(s[nf][0], s[nf][1]));
            tmax_hi = fmaxf(tmax_hi, fmaxf(s[nf][2], s[nf][3]));
        }
        tmax_lo = fmaxf(tmax_lo, __shfl_xor_sync(0xffffffffu, tmax_lo, 1));
        tmax_lo = fmaxf(tmax_lo, __shfl_xor_sync(0xffffffffu, tmax_lo, 2));
        tmax_hi = fmaxf(tmax_hi, __shfl_xor_sync(0xffffffffu, tmax_hi, 1));
        tmax_hi = fmaxf(tmax_hi, __shfl_xor_sync(0xffffffffu, tmax_hi, 2));

        float mn_lo = fmaxf(m_lo, tmax_lo);
        float mn_hi = fmaxf(m_hi, tmax_hi);
        float a_lo = __expf(m_lo - mn_lo);
        float a_hi = __expf(m_hi - mn_hi);

        unsigned* Psm = asmem;
        float sum_lo = 0.f, sum_hi = 0.f;
        #pragma unroll
        for (int nf = 0; nf < 8; nf++) {
            float p0 = __expf(s[nf][0] - mn_lo);
            float p1 = __expf(s[nf][1] - mn_lo);
            float p2 = __expf(s[nf][2] - mn_hi);
            float p3 = __expf(s[nf][3] - mn_hi);
            sum_lo += p0 + p1;
            sum_hi += p2 + p3;
            uint2 plo, phi;
            plo.x = f2tf(p0); plo.y = f2tf(p1);
            phi.x = f2tf(p2); phi.y = f2tf(p3);
            *(uint2*)&Psm[(r0 + g) * KST + nf * 8 + 2 * tg]     = plo;
            *(uint2*)&Psm[(r0 + g + 8) * KST + nf * 8 + 2 * tg] = phi;
            o[nf][0] *= a_lo; o[nf][1] *= a_lo;
            o[nf][2] *= a_hi; o[nf][3] *= a_hi;
        }
        sum_lo += __shfl_xor_sync(0xffffffffu, sum_lo, 1);
        sum_lo += __shfl_xor_sync(0xffffffffu, sum_lo, 2);
        sum_hi += __shfl_xor_sync(0xffffffffu, sum_hi, 1);
        sum_hi += __shfl_xor_sync(0xffffffffu, sum_hi, 2);
        l_lo = l_lo * a_lo + sum_lo;
        l_hi = l_hi * a_hi + sum_hi;
        m_lo = mn_lo; m_hi = mn_hi;
        __syncwarp();                      // P visible within warp

        // ---- O += P V ----
        #pragma unroll
        for (int kk = 0; kk < 8; kk++) {
            unsigned pa[4];
            unsigned addr = p_base + 4 * (r0 * KST + kk * 8 + pf_lane);
            ldsm_x4(pa[0], pa[1], pa[2], pa[3], addr);
            #pragma unroll
            for (int nf = 0; nf < 8; nf++) {
                unsigned b0 = Vsm[(kk * 8 + tg) * VST + nf * 8 + g];
                unsigned b1 = Vsm[(kk * 8 + tg + 4) * VST + nf * 8 + g];
                mma_tf32(o[nf], pa, b0, b1);
            }
        }
        __syncthreads();                   // all warps done with K/V[bsel] before overwrite
    }
#undef AISSUE

    float inv_lo = 1.f / l_lo;
    float inv_hi = 1.f / l_hi;
    const int qrow_lo = blockIdx.x * 128 + r0 + g;
    float* out_lo = g_attn + ((size_t)b * Ssz + qrow_lo) * Esz + h * Dsz;
    float* out_hi = out_lo + 8 * Esz;
    #pragma unroll
    for (int nf = 0; nf < 8; nf++) {
        int col = nf * 8 + 2 * tg;
        float2 wlo, whi;
        wlo.x = roundtf(o[nf][0] * inv_lo); wlo.y = roundtf(o[nf][1] * inv_lo);
        whi.x = roundtf(o[nf][2] * inv_hi); whi.y = roundtf(o[nf][3] * inv_hi);
        *(float2*)(out_lo + col) = wlo;
        *(float2*)(out_hi + col) = whi;
    }
}

// ---------------- launch ----------------
extern "C" void kernel_launch(void* const* d_in, const int* in_sizes, int n_in,
                              void* d_out, int out_size)
{
    const float* X  = (const float*)d_in[0];
    const float* Wq = (const float*)d_in[1];
    const float* bq = (const float*)d_in[2];
    const float* Wk = (const float*)d_in[3];
    const float* bk = (const float*)d_in[4];
    const float* Wv = (const float*)d_in[5];
    const float* bv = (const float*)d_in[6];
    const float* Wo = (const float*)d_in[7];
    const float* bo = (const float*)d_in[8];
    float* out = (float*)d_out;

    (void)cudaFuncSetAttribute(gemm_ca, cudaFuncAttributeMaxDynamicSharedMemorySize, GSMEM);
    (void)cudaFuncSetAttribute(attn_kernel, cudaFuncAttributeMaxDynamicSharedMemorySize, ATTN_SMEM);

    // one-time rounding / layout conversions
    conv_round<<<(Msz * Esz) / (256 * 4), 256>>>(X);
    conv_wqkvT<<<3 * Esz, 128>>>(Wq, Wk, Wv);
    conv_woT<<<Esz, 128>>>(Wo);

    // QKV projection (tf32 mma + cp.async 3-stage pipeline, Kc=32)
    gemm_ca<<<dim3(18, 64), 256, GSMEM>>>(bq, bk, bv, nullptr, 0);

    // attention (Br=128, cp.async double-buffered K/V)
    attn_kernel<<<dim3(Ssz / 128, Bsz * Hsz), 256, ATTN_SMEM>>>();

    // output projection
    gemm_ca<<<dim3(6, 64), 256, GSMEM>>>(bo, nullptr, nullptr, out, 1);
}

// round 14
// speedup vs baseline: 1.2613x; 1.2613x over previous
#include <cuda_runtime.h>
#include <cuda_fp16.h>
#include <cstdint>

#define Bsz 8
#define Ssz 1024
#define Esz 768
#define Hsz 12
#define Dsz 64
#define Msz (Bsz*Ssz)   // 8192

// ---------------- scratch (device globals; referenced ONLY in device code) ----------------
__device__ __half g_qh[Bsz*Hsz*Ssz*Dsz];    // fp16 q (pre-scaled 0.125)
__device__ __half g_kh[Bsz*Hsz*Ssz*Dsz];    // fp16 k
__device__ __half g_vh[Bsz*Hsz*Ssz*Dsz];    // fp16 v
__device__ __half g_ah[(size_t)Msz*Esz];    // fp16 attention output [B*S][E]
__device__ __half g_xh[(size_t)Msz*Esz];    // fp16 X
__device__ __half g_wTh[(size_t)(3*Esz)*Esz]; // fp16 W^T [2304][768], q rows pre-scaled
__device__ __half g_woTh[(size_t)Esz*Esz];  // fp16 Wo^T [768][768]

// ---------------- helpers ----------------
__device__ __forceinline__ void mma_f16(float* c, const unsigned* a, unsigned b0, unsigned b1) {
    asm volatile(
        "mma.sync.aligned.m16n8k16.row.col.f32.f16.f16.f32 "
        "{%0,%1,%2,%3}, {%4,%5,%6,%7}, {%8,%9}, {%0,%1,%2,%3};"
        : "+f"(c[0]), "+f"(c[1]), "+f"(c[2]), "+f"(c[3])
        : "r"(a[0]), "r"(a[1]), "r"(a[2]), "r"(a[3]), "r"(b0), "r"(b1));
}
__device__ __forceinline__ void ldsm_x4(unsigned& r0, unsigned& r1, unsigned& r2, unsigned& r3,
                                        unsigned saddr) {
    asm volatile("ldmatrix.sync.aligned.m8n8.x4.shared.b16 {%0,%1,%2,%3}, [%4];"
        : "=r"(r0), "=r"(r1), "=r"(r2), "=r"(r3) : "r"(saddr));
}
__device__ __forceinline__ void ldsm_x4t(unsigned& r0, unsigned& r1, unsigned& r2, unsigned& r3,
                                         unsigned saddr) {
    asm volatile("ldmatrix.sync.aligned.m8n8.x4.trans.shared.b16 {%0,%1,%2,%3}, [%4];"
        : "=r"(r0), "=r"(r1), "=r"(r2), "=r"(r3) : "r"(saddr));
}
__device__ __forceinline__ unsigned smem_u32(const void* p) {
    unsigned a;
    asm("{ .reg .u64 t; cvta.to.shared.u64 t, %1; cvt.u32.u64 %0, t; }" : "=r"(a) : "l"(p));
    return a;
}
__device__ __forceinline__ void cp16(unsigned dst, const void* src) {
    asm volatile("cp.async.cg.shared.global [%0], [%1], 16;" :: "r"(dst), "l"(src));
}
#define CP_COMMIT()  asm volatile("cp.async.commit_group;" ::: "memory")
#define CP_WAIT1()   asm volatile("cp.async.wait_group 1;" ::: "memory")

// ============================================================================
// Conversion kernels (one-time). fp32 -> fp16.
// ============================================================================
__global__ __launch_bounds__(256) void conv_x(const float* __restrict__ src)
{
    int i = (blockIdx.x * 256 + threadIdx.x) * 8;
    float4 a = *(const float4*)(src + i);
    float4 b = *(const float4*)(src + i + 4);
    __align__(16) __half h[8];
    h[0] = __float2half_rn(a.x); h[1] = __float2half_rn(a.y);
    h[2] = __float2half_rn(a.z); h[3] = __float2half_rn(a.w);
    h[4] = __float2half_rn(b.x); h[5] = __float2half_rn(b.y);
    h[6] = __float2half_rn(b.z); h[7] = __float2half_rn(b.w);
    *(uint4*)(g_xh + i) = *(uint4*)h;
}

// W^T row n (0..2303): which = n/768, head = (n%768)>>6, d = n&63; q rows scaled 0.125
__global__ __launch_bounds__(128) void conv_wqkvT(const float* __restrict__ Wq,
                                                  const float* __restrict__ Wk,
                                                  const float* __restrict__ Wv)
{
    int n = blockIdx.x;
    int which = n / Esz, rem = n % Esz, h = rem >> 6, d = rem & 63;
    const float* W = (which == 0) ? Wq : (which == 1 ? Wk : Wv);
    const float sc = (which == 0) ? 0.125f : 1.0f;
    const float* col = W + (size_t)h * Esz * Dsz + d;
    __half* row = g_wTh + (size_t)n * Esz;
    for (int e = threadIdx.x; e < Esz; e += 128)
        row[e] = __float2half_rn(col[(size_t)e * Dsz] * sc);
}

__global__ __launch_bounds__(128) void conv_woT(const float* __restrict__ Wo)
{
    int n = blockIdx.x;
    __half* row = g_woTh + (size_t)n * Esz;
    for (int e = threadIdx.x; e < Esz; e += 128)
        row[e] = __float2half_rn(Wo[(size_t)e * Esz + n]);
}

// ============================================================================
// fp16 GEMM, 3-stage cp.async pipeline, Kc=64 halves (12 chunks).
// Tile 128M x 128N, 8 warps (2m x 4n), warp 64x32, m16n8k16.
//   mode 0: A=g_xh, Bt=g_wTh -> qkv (per-head bias, fp16 scatter to g_qh/kh/vh)
//   mode 1: A=g_ah, Bt=g_woTh -> oproj (bias bo, fp32 row-major Out)
// ============================================================================
#define GST 72                            // smem stride in halves (144B = 9x16B units)
#define STG_BYTES (128*GST*2*2)           // A + B = 36864 B
#define AOFFB (128*GST*2)                 // B area byte offset in a stage = 18432
#define GSMEM (3*STG_BYTES)               // 110592
#define CHUNKS 12

__global__ __launch_bounds__(256, 2) void gemm_h(
    const float* __restrict__ b0p, const float* __restrict__ b1p,
    const float* __restrict__ b2p,
    float* __restrict__ Out, int mode)
{
    extern __shared__ __align__(16) char smem[];
    const unsigned sbase = smem_u32(smem);

    const __half* A  = (mode == 0) ? g_xh  : g_ah;
    const __half* Bt = (mode == 0) ? g_wTh : g_woTh;

    const int t    = threadIdx.x;
    const int warp = t >> 5;
    const int lane = t & 31;
    const int g    = lane >> 2;
    const int tg   = lane & 3;
    const int wm   = (warp & 1) * 64;
    const int wn   = (warp >> 1) * 32;
    const int n0   = blockIdx.x * 128;
    const int m0   = blockIdx.y * 128;

    // one lane-offset pattern serves A, B (halves): rows lane&15, col-half (lane>>4)*8
    const unsigned xl = (lane & 15) * GST + (lane >> 4) * 8;

    // global loads: thread covers row t>>1, 4 of 8 16B-lines per matrix
    const int row_ = t >> 1;
    const int sb_  = (t & 1) * 4;
    const __half* Ag = A  + (size_t)(m0 + row_) * Esz;
    const __half* Bg = Bt + (size_t)(n0 + row_) * Esz;

#define GISSUE(chunk, buf) do {                                               \
    const unsigned s0 = sbase + (unsigned)(buf) * STG_BYTES;                  \
    const int c0 = (chunk) * 64;                                              \
    _Pragma("unroll")                                                         \
    for (int it = 0; it < 4; it++) {                                          \
        const int seg = sb_ + it;                                             \
        cp16(s0 + (unsigned)(row_ * GST + seg * 8) * 2, Ag + c0 + seg * 8);   \
        cp16(s0 + AOFFB + (unsigned)(row_ * GST + seg * 8) * 2, Bg + c0 + seg * 8); \
    }                                                                         \
} while (0)

    GISSUE(0, 0); CP_COMMIT();
    GISSUE(1, 1); CP_COMMIT();

    float acc[4][4][4];
    #pragma unroll
    for (int mi = 0; mi < 4; mi++)
        #pragma unroll
        for (int ni = 0; ni < 4; ni++)
            #pragma unroll
            for (int j = 0; j < 4; j++) acc[mi][ni][j] = 0.f;

    int buf = 0, buf2 = 2;
    for (int i = 0; i < CHUNKS; i++) {
        CP_WAIT1();
        __syncthreads();
        if (i + 2 < CHUNKS) GISSUE(i + 2, buf2);
        CP_COMMIT();

        const unsigned sA = sbase + (unsigned)buf * STG_BYTES;
        const unsigned sB = sA + AOFFB;

        #pragma unroll
        for (int ks = 0; ks < 4; ks++) {           // k-steps of 16 halves
            unsigned bfr[2][4];
            #pragma unroll
            for (int nip = 0; nip < 2; nip++)      // each x4 feeds 2 n-groups
                ldsm_x4(bfr[nip][0], bfr[nip][1], bfr[nip][2], bfr[nip][3],
                        sB + 2 * ((wn + nip * 16) * GST + ks * 16 + xl));
            unsigned a[4][4];
            #pragma unroll
            for (int mi = 0; mi < 4; mi++)
                ldsm_x4(a[mi][0], a[mi][1], a[mi][2], a[mi][3],
                        sA + 2 * ((wm + mi * 16) * GST + ks * 16 + xl));
            #pragma unroll
            for (int nip = 0; nip < 2; nip++)
                #pragma unroll
                for (int mi = 0; mi < 4; mi++) {
                    mma_f16(acc[mi][2 * nip],     a[mi], bfr[nip][0], bfr[nip][2]);
                    mma_f16(acc[mi][2 * nip + 1], a[mi], bfr[nip][1], bfr[nip][3]);
                }
        }
        buf  = (buf  == 2) ? 0 : buf + 1;
        buf2 = (buf2 == 2) ? 0 : buf2 + 1;
    }
#undef GISSUE

    // ---- epilogue ----
    if (mode == 0) {
        const int which = n0 / Esz;
        const float* bias = (which == 0) ? b0p : (which == 1 ? b1p : b2p);
        __half* OUTsel    = (which == 0) ? g_qh : (which == 1 ? g_kh : g_vh);
        const float bsc   = (which == 0) ? 0.125f : 1.0f;
        const int nrel = n0 % Esz;
        #pragma unroll
        for (int mi = 0; mi < 4; mi++) {
            const int row_lo = m0 + wm + mi * 16 + g;
            const int row_hi = row_lo + 8;
            const int blo = row_lo >> 10, slo = row_lo & 1023;
            const int bhi = row_hi >> 10, shi = row_hi & 1023;
            #pragma unroll
            for (int ni = 0; ni < 4; ni++) {
                const int nc = nrel + wn + ni * 8 + 2 * tg;
                const int head = nc >> 6, d = nc & 63;
                float2 bb = *(const float2*)(bias + head * Dsz + d);
                bb.x *= bsc; bb.y *= bsc;
                __half* olo = OUTsel + ((((size_t)blo * Hsz + head) << 10) + slo) * Dsz + d;
                __half* ohi = OUTsel + ((((size_t)bhi * Hsz + head) << 10) + shi) * Dsz + d;
                *(__half2*)olo = __floats2half2_rn(acc[mi][ni][0] + bb.x, acc[mi][ni][1] + bb.y);
                *(__half2*)ohi = __floats2half2_rn(acc[mi][ni][2] + bb.x, acc[mi][ni][3] + bb.y);
            }
        }
    } else {
        #pragma unroll
        for (int mi = 0; mi < 4; mi++) {
            const int row_lo = m0 + wm + mi * 16 + g;
            float* olo = Out + (size_t)row_lo * Esz + n0;
            float* ohi = olo + (size_t)8 * Esz;
            #pragma unroll
            for (int ni = 0; ni < 4; ni++) {
                const int col = wn + ni * 8 + 2 * tg;
                float2 bb = *(const float2*)(b0p + n0 + col);
                float2 wlo, whi;
                wlo.x = acc[mi][ni][0] + bb.x; wlo.y = acc[mi][ni][1] + bb.y;
                whi.x = acc[mi][ni][2] + bb.x; whi.y = acc[mi][ni][3] + bb.y;
                *(float2*)(olo + col) = wlo;
                *(float2*)(ohi + col) = whi;
            }
        }
    }
}

// ============================================================================
// Flash attention fp16, Br=128, 8 warps, synchronous tiles (R12 structure),
// separate P buffer (no K/P hazard barrier). Static smem 36.9 KB.
// Layout (halves): P[128][72] | K[64][72] | V[64][72]
// ============================================================================
#define AT 72   // stride halves for P/K/V

__global__ __launch_bounds__(256) void attn_kernel()
{
    __shared__ __align__(16) __half Psm[128 * AT];
    __shared__ __align__(16) __half Ksm[64 * AT];
    __shared__ __align__(16) __half Vsm[64 * AT];

    const int bh = blockIdx.y;
    const int b = bh / Hsz, h = bh % Hsz;
    const int tid  = threadIdx.x;
    const int warp = tid >> 5;
    const int lane = tid & 31;
    const int g  = lane >> 2;
    const int tg = lane & 3;
    const int r0 = warp * 16;

    const unsigned p_base = smem_u32(Psm);
    const unsigned k_base = smem_u32(Ksm);
    const unsigned v_base = smem_u32(Vsm);
    const unsigned xl = (lane & 15) * AT + (lane >> 4) * 8;   // shared lane offset (halves)

    // ---- stage Q (scaled fp16) rows 0-127 into P buffer ----
    {
        const uint4* Qg = (const uint4*)(g_qh + ((size_t)bh * Ssz + blockIdx.x * 128) * Dsz);
        #pragma unroll
        for (int i = 0; i < 4; i++) {
            int idx = i * 256 + tid;        // 1024 lines (8 halves each)
            int row = idx >> 3, c = (idx & 7) * 8;
            *(uint4*)&Psm[row * AT + c] = Qg[idx];
        }
    }
    __syncthreads();

    unsigned qa[4][4];
    #pragma unroll
    for (int kk = 0; kk < 4; kk++)
        ldsm_x4(qa[kk][0], qa[kk][1], qa[kk][2], qa[kk][3],
                p_base + 2 * (r0 * AT + kk * 16 + xl));
    __syncthreads();                        // Q extracted; P buffer free

    float o[8][4];
    #pragma unroll
    for (int nf = 0; nf < 8; nf++)
        #pragma unroll
        for (int j = 0; j < 4; j++) o[nf][j] = 0.f;
    float m_lo = -1e30f, m_hi = -1e30f, l_lo = 0.f, l_hi = 0.f;

    const uint4* Kg0 = (const uint4*)(g_kh + (size_t)bh * (Ssz * Dsz));
    const uint4* Vg0 = (const uint4*)(g_vh + (size_t)bh * (Ssz * Dsz));

    for (int kb = 0; kb < Ssz / 64; kb++) {
        const uint4* Kg = Kg0 + kb * 512;   // 64*64 halves = 512 lines
        const uint4* Vg = Vg0 + kb * 512;
        #pragma unroll
        for (int i = 0; i < 2; i++) {
            int idx = i * 256 + tid;
            int row = idx >> 3, c = (idx & 7) * 8;
            *(uint4*)&Ksm[row * AT + c] = Kg[idx];
            *(uint4*)&Vsm[row * AT + c] = Vg[idx];
        }
        __syncthreads();

        // ---- S = Q K^T ----
        float s[8][4];
        #pragma unroll
        for (int nf = 0; nf < 8; nf++)
            #pragma unroll
            for (int j = 0; j < 4; j++) s[nf][j] = 0.f;

        #pragma unroll
        for (int nfp = 0; nfp < 4; nfp++) {          // each x4 feeds 2 n-groups
            #pragma unroll
            for (int kk = 0; kk < 4; kk++) {
                unsigned kb0, kb1, kb2, kb3;
                ldsm_x4(kb0, kb1, kb2, kb3,
                        k_base + 2 * ((nfp * 16) * AT + kk * 16 + xl));
                mma_f16(s[2 * nfp],     qa[kk], kb0, kb2);
                mma_f16(s[2 * nfp + 1], qa[kk], kb1, kb3);
            }
        }

        // ---- online softmax ----
        float tmax_lo = -1e30f, tmax_hi = -1e30f;
        #pragma unroll
        for (int nf = 0; nf < 8; nf++) {
            tmax_lo = fmaxf(tmax_lo, fmaxf(s[nf][0], s[nf][1]));
            tmax_hi = fmaxf(tmax_hi, fmaxf(s[nf][2], s[nf][3]));
        }
        tmax_lo = fmaxf(tmax_lo, __shfl_xor_sync(0xffffffffu, tmax_lo, 1));
        tmax_lo = fmaxf(tmax_lo, __shfl_xor_sync(0xffffffffu, tmax_lo, 2));
        tmax_hi = fmaxf(tmax_hi, __shfl_xor_sync(0xffffffffu, tmax_hi, 1));
        tmax_hi = fmaxf(tmax_hi, __shfl_xor_sync(0xffffffffu, tmax_hi, 2));

        float mn_lo = fmaxf(m_lo, tmax_lo);
        float mn_hi = fmaxf(m_hi, tmax_hi);
        float a_lo = __expf(m_lo - mn_lo);
        float a_hi = __expf(m_hi - mn_hi);

        float sum_lo = 0.f, sum_hi = 0.f;
        #pragma unroll
        for (int nf = 0; nf < 8; nf++) {
            float p0 = __expf(s[nf][0] - mn_lo);
            float p1 = __expf(s[nf][1] - mn_lo);
            float p2 = __expf(s[nf][2] - mn_hi);
            float p3 = __expf(s[nf][3] - mn_hi);
            sum_lo += p0 + p1;
            sum_hi += p2 + p3;
            *(__half2*)&Psm[(r0 + g) * AT + nf * 8 + 2 * tg]     = __floats2half2_rn(p0, p1);
            *(__half2*)&Psm[(r0 + g + 8) * AT + nf * 8 + 2 * tg] = __floats2half2_rn(p2, p3);
            o[nf][0] *= a_lo; o[nf][1] *= a_lo;
            o[nf][2] *= a_hi; o[nf][3] *= a_hi;
        }
        sum_lo += __shfl_xor_sync(0xffffffffu, sum_lo, 1);
        sum_lo += __shfl_xor_sync(0xffffffffu, sum_lo, 2);
        sum_hi += __shfl_xor_sync(0xffffffffu, sum_hi, 1);
        sum_hi += __shfl_xor_sync(0xffffffffu, sum_hi, 2);
        l_lo = l_lo * a_lo + sum_lo;
        l_hi = l_hi * a_hi + sum_hi;
        m_lo = mn_lo; m_hi = mn_hi;
        __syncwarp();                       // P visible within warp

        // ---- O += P V : P via ldsm, V via ldsm.trans ----
        #pragma unroll
        for (int kk = 0; kk < 4; kk++) {    // keys in steps of 16
            unsigned pa[4];
            ldsm_x4(pa[0], pa[1], pa[2], pa[3],
                    p_base + 2 * (r0 * AT + kk * 16 + xl));
            #pragma unroll
            for (int nfp = 0; nfp < 4; nfp++) {
                unsigned v0, v1, v2, v3;
                ldsm_x4t(v0, v1, v2, v3,
                         v_base + 2 * ((kk * 16 + (lane & 15)) * AT + nfp * 16 + (lane >> 4) * 8));
                mma_f16(o[2 * nfp],     pa, v0, v1);
                mma_f16(o[2 * nfp + 1], pa, v2, v3);
            }
        }
        __syncthreads();                    // all warps done with K/V before overwrite
    }

    float inv_lo = 1.f / l_lo;
    float inv_hi = 1.f / l_hi;
    const int qrow_lo = blockIdx.x * 128 + r0 + g;
    __half* out_lo = g_ah + ((size_t)b * Ssz + qrow_lo) * Esz + h * Dsz;
    __half* out_hi = out_lo + 8 * Esz;
    #pragma unroll
    for (int nf = 0; nf < 8; nf++) {
        int col = nf * 8 + 2 * tg;
        *(__half2*)(out_lo + col) = __floats2half2_rn(o[nf][0] * inv_lo, o[nf][1] * inv_lo);
        *(__half2*)(out_hi + col) = __floats2half2_rn(o[nf][2] * inv_hi, o[nf][3] * inv_hi);
    }
}

// ---------------- launch ----------------
extern "C" void kernel_launch(void* const* d_in, const int* in_sizes, int n_in,
                              void* d_out, int out_size)
{
    const float* X  = (const float*)d_in[0];
    const float* Wq = (const float*)d_in[1];
    const float* bq = (const float*)d_in[2];
    const float* Wk = (const float*)d_in[3];
    const float* bk = (const float*)d_in[4];
    const float* Wv = (const float*)d_in[5];
    const float* bv = (const float*)d_in[6];
    const float* Wo = (const float*)d_in[7];
    const float* bo = (const float*)d_in[8];
    float* out = (float*)d_out;

    (void)cudaFuncSetAttribute(gemm_h, cudaFuncAttributeMaxDynamicSharedMemorySize, GSMEM);

    // one-time fp16 conversions
    conv_x<<<(Msz * Esz) / (256 * 8), 256>>>(X);
    conv_wqkvT<<<3 * Esz, 128>>>(Wq, Wk, Wv);
    conv_woT<<<Esz, 128>>>(Wo);

    // QKV projection (fp16 mma + cp.async 3-stage, Kc=64)
    gemm_h<<<dim3(18, 64), 256, GSMEM>>>(bq, bk, bv, nullptr, 0);

    // attention (Br=128, fp16)
    attn_kernel<<<dim3(Ssz / 128, Bsz * Hsz), 256>>>();

    // output projection
    gemm_h<<<dim3(6, 64), 256, GSMEM>>>(bo, nullptr, nullptr, out, 1);
}

// round 15
// speedup vs baseline: 1.3379x; 1.0607x over previous
#include <cuda_runtime.h>
#include <cuda_fp16.h>
#include <cstdint>

#define Bsz 8
#define Ssz 1024
#define Esz 768
#define Hsz 12
#define Dsz 64
#define Msz (Bsz*Ssz)   // 8192

// ---------------- scratch (device globals; referenced ONLY in device code) ----------------
__device__ __half g_qh[Bsz*Hsz*Ssz*Dsz];    // fp16 q (pre-scaled 0.125)
__device__ __half g_kh[Bsz*Hsz*Ssz*Dsz];    // fp16 k
__device__ __half g_vh[Bsz*Hsz*Ssz*Dsz];    // fp16 v
__device__ __half g_ah[(size_t)Msz*Esz];    // fp16 attention output [B*S][E]
__device__ __half g_xh[(size_t)Msz*Esz];    // fp16 X
__device__ __half g_wTh[(size_t)(3*Esz)*Esz]; // fp16 W^T [2304][768], q rows pre-scaled
__device__ __half g_woTh[(size_t)Esz*Esz];  // fp16 Wo^T [768][768]

// ---------------- helpers ----------------
__device__ __forceinline__ void mma_f16(float* c, const unsigned* a, unsigned b0, unsigned b1) {
    asm volatile(
        "mma.sync.aligned.m16n8k16.row.col.f32.f16.f16.f32 "
        "{%0,%1,%2,%3}, {%4,%5,%6,%7}, {%8,%9}, {%0,%1,%2,%3};"
        : "+f"(c[0]), "+f"(c[1]), "+f"(c[2]), "+f"(c[3])
        : "r"(a[0]), "r"(a[1]), "r"(a[2]), "r"(a[3]), "r"(b0), "r"(b1));
}
__device__ __forceinline__ void ldsm_x4(unsigned& r0, unsigned& r1, unsigned& r2, unsigned& r3,
                                        unsigned saddr) {
    asm volatile("ldmatrix.sync.aligned.m8n8.x4.shared.b16 {%0,%1,%2,%3}, [%4];"
        : "=r"(r0), "=r"(r1), "=r"(r2), "=r"(r3) : "r"(saddr));
}
__device__ __forceinline__ void ldsm_x4t(unsigned& r0, unsigned& r1, unsigned& r2, unsigned& r3,
                                         unsigned saddr) {
    asm volatile("ldmatrix.sync.aligned.m8n8.x4.trans.shared.b16 {%0,%1,%2,%3}, [%4];"
        : "=r"(r0), "=r"(r1), "=r"(r2), "=r"(r3) : "r"(saddr));
}
__device__ __forceinline__ unsigned smem_u32(const void* p) {
    unsigned a;
    asm("{ .reg .u64 t; cvta.to.shared.u64 t, %1; cvt.u32.u64 %0, t; }" : "=r"(a) : "l"(p));
    return a;
}
__device__ __forceinline__ void cp16(unsigned dst, const void* src) {
    asm volatile("cp.async.cg.shared.global [%0], [%1], 16;" :: "r"(dst), "l"(src));
}
#define CP_COMMIT()  asm volatile("cp.async.commit_group;" ::: "memory")
#define CP_WAIT1()   asm volatile("cp.async.wait_group 1;" ::: "memory")

// ============================================================================
// Conversion kernels (one-time). fp32 -> fp16.
// ============================================================================
__global__ __launch_bounds__(256) void conv_x(const float* __restrict__ src)
{
    int i = (blockIdx.x * 256 + threadIdx.x) * 8;
    float4 a = *(const float4*)(src + i);
    float4 b = *(const float4*)(src + i + 4);
    __align__(16) __half h[8];
    h[0] = __float2half_rn(a.x); h[1] = __float2half_rn(a.y);
    h[2] = __float2half_rn(a.z); h[3] = __float2half_rn(a.w);
    h[4] = __float2half_rn(b.x); h[5] = __float2half_rn(b.y);
    h[6] = __float2half_rn(b.z); h[7] = __float2half_rn(b.w);
    *(uint4*)(g_xh + i) = *(uint4*)h;
}

__global__ __launch_bounds__(128) void conv_wqkvT(const float* __restrict__ Wq,
                                                  const float* __restrict__ Wk,
                                                  const float* __restrict__ Wv)
{
    int n = blockIdx.x;
    int which = n / Esz, rem = n % Esz, h = rem >> 6, d = rem & 63;
    const float* W = (which == 0) ? Wq : (which == 1 ? Wk : Wv);
    const float sc = (which == 0) ? 0.125f : 1.0f;
    const float* col = W + (size_t)h * Esz * Dsz + d;
    __half* row = g_wTh + (size_t)n * Esz;
    for (int e = threadIdx.x; e < Esz; e += 128)
        row[e] = __float2half_rn(col[(size_t)e * Dsz] * sc);
}

__global__ __launch_bounds__(128) void conv_woT(const float* __restrict__ Wo)
{
    int n = blockIdx.x;
    __half* row = g_woTh + (size_t)n * Esz;
    for (int e = threadIdx.x; e < Esz; e += 128)
        row[e] = __float2half_rn(Wo[(size_t)e * Esz + n]);
}

// ============================================================================
// fp16 GEMM, 3-stage cp.async pipeline, Kc=64 — UNCHANGED from R14 (proven).
// ============================================================================
#define GST 72
#define STG_BYTES (128*GST*2*2)           // 36864
#define AOFFB (128*GST*2)                 // 18432
#define GSMEM (3*STG_BYTES)               // 110592
#define CHUNKS 12

__global__ __launch_bounds__(256, 2) void gemm_h(
    const float* __restrict__ b0p, const float* __restrict__ b1p,
    const float* __restrict__ b2p,
    float* __restrict__ Out, int mode)
{
    extern __shared__ __align__(16) char smem[];
    const unsigned sbase = smem_u32(smem);

    const __half* A  = (mode == 0) ? g_xh  : g_ah;
    const __half* Bt = (mode == 0) ? g_wTh : g_woTh;

    const int t    = threadIdx.x;
    const int warp = t >> 5;
    const int lane = t & 31;
    const int g    = lane >> 2;
    const int tg   = lane & 3;
    const int wm   = (warp & 1) * 64;
    const int wn   = (warp >> 1) * 32;
    const int n0   = blockIdx.x * 128;
    const int m0   = blockIdx.y * 128;

    const unsigned xl = (lane & 15) * GST + (lane >> 4) * 8;

    const int row_ = t >> 1;
    const int sb_  = (t & 1) * 4;
    const __half* Ag = A  + (size_t)(m0 + row_) * Esz;
    const __half* Bg = Bt + (size_t)(n0 + row_) * Esz;

#define GISSUE(chunk, buf) do {                                               \
    const unsigned s0 = sbase + (unsigned)(buf) * STG_BYTES;                  \
    const int c0 = (chunk) * 64;                                              \
    _Pragma("unroll")                                                         \
    for (int it = 0; it < 4; it++) {                                          \
        const int seg = sb_ + it;                                             \
        cp16(s0 + (unsigned)(row_ * GST + seg * 8) * 2, Ag + c0 + seg * 8);   \
        cp16(s0 + AOFFB + (unsigned)(row_ * GST + seg * 8) * 2, Bg + c0 + seg * 8); \
    }                                                                         \
} while (0)

    GISSUE(0, 0); CP_COMMIT();
    GISSUE(1, 1); CP_COMMIT();

    float acc[4][4][4];
    #pragma unroll
    for (int mi = 0; mi < 4; mi++)
        #pragma unroll
        for (int ni = 0; ni < 4; ni++)
            #pragma unroll
            for (int j = 0; j < 4; j++) acc[mi][ni][j] = 0.f;

    int buf = 0, buf2 = 2;
    for (int i = 0; i < CHUNKS; i++) {
        CP_WAIT1();
        __syncthreads();
        if (i + 2 < CHUNKS) GISSUE(i + 2, buf2);
        CP_COMMIT();

        const unsigned sA = sbase + (unsigned)buf * STG_BYTES;
        const unsigned sB = sA + AOFFB;

        #pragma unroll
        for (int ks = 0; ks < 4; ks++) {
            unsigned bfr[2][4];
            #pragma unroll
            for (int nip = 0; nip < 2; nip++)
                ldsm_x4(bfr[nip][0], bfr[nip][1], bfr[nip][2], bfr[nip][3],
                        sB + 2 * ((wn + nip * 16) * GST + ks * 16 + xl));
            unsigned a[4][4];
            #pragma unroll
            for (int mi = 0; mi < 4; mi++)
                ldsm_x4(a[mi][0], a[mi][1], a[mi][2], a[mi][3],
                        sA + 2 * ((wm + mi * 16) * GST + ks * 16 + xl));
            #pragma unroll
            for (int nip = 0; nip < 2; nip++)
                #pragma unroll
                for (int mi = 0; mi < 4; mi++) {
                    mma_f16(acc[mi][2 * nip],     a[mi], bfr[nip][0], bfr[nip][2]);
                    mma_f16(acc[mi][2 * nip + 1], a[mi], bfr[nip][1], bfr[nip][3]);
                }
        }
        buf  = (buf  == 2) ? 0 : buf + 1;
        buf2 = (buf2 == 2) ? 0 : buf2 + 1;
    }
#undef GISSUE

    if (mode == 0) {
        const int which = n0 / Esz;
        const float* bias = (which == 0) ? b0p : (which == 1 ? b1p : b2p);
        __half* OUTsel    = (which == 0) ? g_qh : (which == 1 ? g_kh : g_vh);
        const float bsc   = (which == 0) ? 0.125f : 1.0f;
        const int nrel = n0 % Esz;
        #pragma unroll
        for (int mi = 0; mi < 4; mi++) {
            const int row_lo = m0 + wm + mi * 16 + g;
            const int row_hi = row_lo + 8;
            const int blo = row_lo >> 10, slo = row_lo & 1023;
            const int bhi = row_hi >> 10, shi = row_hi & 1023;
            #pragma unroll
            for (int ni = 0; ni < 4; ni++) {
                const int nc = nrel + wn + ni * 8 + 2 * tg;
                const int head = nc >> 6, d = nc & 63;
                float2 bb = *(const float2*)(bias + head * Dsz + d);
                bb.x *= bsc; bb.y *= bsc;
                __half* olo = OUTsel + ((((size_t)blo * Hsz + head) << 10) + slo) * Dsz + d;
                __half* ohi = OUTsel + ((((size_t)bhi * Hsz + head) << 10) + shi) * Dsz + d;
                *(__half2*)olo = __floats2half2_rn(acc[mi][ni][0] + bb.x, acc[mi][ni][1] + bb.y);
                *(__half2*)ohi = __floats2half2_rn(acc[mi][ni][2] + bb.x, acc[mi][ni][3] + bb.y);
            }
        }
    } else {
        #pragma unroll
        for (int mi = 0; mi < 4; mi++) {
            const int row_lo = m0 + wm + mi * 16 + g;
            float* olo = Out + (size_t)row_lo * Esz + n0;
            float* ohi = olo + (size_t)8 * Esz;
            #pragma unroll
            for (int ni = 0; ni < 4; ni++) {
                const int col = wn + ni * 8 + 2 * tg;
                float2 bb = *(const float2*)(b0p + n0 + col);
                float2 wlo, whi;
                wlo.x = acc[mi][ni][0] + bb.x; wlo.y = acc[mi][ni][1] + bb.y;
                whi.x = acc[mi][ni][2] + bb.x; whi.y = acc[mi][ni][3] + bb.y;
                *(float2*)(olo + col) = wlo;
                *(float2*)(ohi + col) = whi;
            }
        }
    }
}

// ============================================================================
// Flash attention fp16, Br=128, 8 warps. 128 keys loaded per barrier round,
// processed as two 64-key subtiles (per-subtile compute identical to R14).
// Dynamic smem (halves): P[128][72] | K[128][72] | V[128][72] = 55296 B.
// ============================================================================
#define AT 72
#define P_OFF 0
#define K_OFF (128*AT)
#define V_OFF (256*AT)
#define ATTN_SMEM (384*AT*2)   // 55296

__global__ __launch_bounds__(256) void attn_kernel()
{
    extern __shared__ __align__(16) __half hsm[];
    __half* Psm = hsm + P_OFF;
    __half* Ksm = hsm + K_OFF;
    __half* Vsm = hsm + V_OFF;

    const int bh = blockIdx.y;
    const int b = bh / Hsz, h = bh % Hsz;
    const int tid  = threadIdx.x;
    const int warp = tid >> 5;
    const int lane = tid & 31;
    const int g  = lane >> 2;
    const int tg = lane & 3;
    const int r0 = warp * 16;

    const unsigned p_base = smem_u32(Psm);
    const unsigned k_base = smem_u32(Ksm);
    const unsigned v_base = smem_u32(Vsm);
    const unsigned xl = (lane & 15) * AT + (lane >> 4) * 8;

    // ---- stage Q (scaled fp16) rows 0-127 into P buffer ----
    {
        const uint4* Qg = (const uint4*)(g_qh + ((size_t)bh * Ssz + blockIdx.x * 128) * Dsz);
        #pragma unroll
        for (int i = 0; i < 4; i++) {
            int idx = i * 256 + tid;
            int row = idx >> 3, c = (idx & 7) * 8;
            *(uint4*)&Psm[row * AT + c] = Qg[idx];
        }
    }
    __syncthreads();

    unsigned qa[4][4];
    #pragma unroll
    for (int kk = 0; kk < 4; kk++)
        ldsm_x4(qa[kk][0], qa[kk][1], qa[kk][2], qa[kk][3],
                p_base + 2 * (r0 * AT + kk * 16 + xl));
    __syncthreads();

    float o[8][4];
    #pragma unroll
    for (int nf = 0; nf < 8; nf++)
        #pragma unroll
        for (int j = 0; j < 4; j++) o[nf][j] = 0.f;
    float m_lo = -1e30f, m_hi = -1e30f, l_lo = 0.f, l_hi = 0.f;

    const uint4* Kg0 = (const uint4*)(g_kh + (size_t)bh * (Ssz * Dsz));
    const uint4* Vg0 = (const uint4*)(g_vh + (size_t)bh * (Ssz * Dsz));

    for (int kb = 0; kb < Ssz / 128; kb++) {   // 8 rounds of 128 keys
        const uint4* Kg = Kg0 + kb * 1024;     // 128*64 halves = 1024 lines
        const uint4* Vg = Vg0 + kb * 1024;
        #pragma unroll
        for (int i = 0; i < 4; i++) {
            int idx = i * 256 + tid;
            int row = idx >> 3, c = (idx & 7) * 8;
            *(uint4*)&Ksm[row * AT + c] = Kg[idx];
            *(uint4*)&Vsm[row * AT + c] = Vg[idx];
        }
        __syncthreads();

        #pragma unroll
        for (int sub = 0; sub < 2; sub++) {
            const int so = sub * 64;           // subtile key offset

            // ---- S = Q K_sub^T ----
            float s[8][4];
            #pragma unroll
            for (int nf = 0; nf < 8; nf++)
                #pragma unroll
                for (int j = 0; j < 4; j++) s[nf][j] = 0.f;

            #pragma unroll
            for (int nfp = 0; nfp < 4; nfp++) {
                #pragma unroll
                for (int kk = 0; kk < 4; kk++) {
                    unsigned kb0, kb1, kb2, kb3;
                    ldsm_x4(kb0, kb1, kb2, kb3,
                            k_base + 2 * ((so + nfp * 16) * AT + kk * 16 + xl));
                    mma_f16(s[2 * nfp],     qa[kk], kb0, kb2);
                    mma_f16(s[2 * nfp + 1], qa[kk], kb1, kb3);
                }
            }

            // ---- online softmax ----
            float tmax_lo = -1e30f, tmax_hi = -1e30f;
            #pragma unroll
            for (int nf = 0; nf < 8; nf++) {
                tmax_lo = fmaxf(tmax_lo, fmaxf(s[nf][0], s[nf][1]));
                tmax_hi = fmaxf(tmax_hi, fmaxf(s[nf][2], s[nf][3]));
            }
            tmax_lo = fmaxf(tmax_lo, __shfl_xor_sync(0xffffffffu, tmax_lo, 1));
            tmax_lo = fmaxf(tmax_lo, __shfl_xor_sync(0xffffffffu, tmax_lo, 2));
            tmax_hi = fmaxf(tmax_hi, __shfl_xor_sync(0xffffffffu, tmax_hi, 1));
            tmax_hi = fmaxf(tmax_hi, __shfl_xor_sync(0xffffffffu, tmax_hi, 2));

            float mn_lo = fmaxf(m_lo, tmax_lo);
            float mn_hi = fmaxf(m_hi, tmax_hi);
            float a_lo = __expf(m_lo - mn_lo);
            float a_hi = __expf(m_hi - mn_hi);

            __syncwarp();                      // prev subtile's P-reads done before P overwrite
            float sum_lo = 0.f, sum_hi = 0.f;
            #pragma unroll
            for (int nf = 0; nf < 8; nf++) {
                float p0 = __expf(s[nf][0] - mn_lo);
                float p1 = __expf(s[nf][1] - mn_lo);
                float p2 = __expf(s[nf][2] - mn_hi);
                float p3 = __expf(s[nf][3] - mn_hi);
                sum_lo += p0 + p1;
                sum_hi += p2 + p3;
                *(__half2*)&Psm[(r0 + g) * AT + nf * 8 + 2 * tg]     = __floats2half2_rn(p0, p1);
                *(__half2*)&Psm[(r0 + g + 8) * AT + nf * 8 + 2 * tg] = __floats2half2_rn(p2, p3);
                o[nf][0] *= a_lo; o[nf][1] *= a_lo;
                o[nf][2] *= a_hi; o[nf][3] *= a_hi;
            }
            sum_lo += __shfl_xor_sync(0xffffffffu, sum_lo, 1);
            sum_lo += __shfl_xor_sync(0xffffffffu, sum_lo, 2);
            sum_hi += __shfl_xor_sync(0xffffffffu, sum_hi, 1);
            sum_hi += __shfl_xor_sync(0xffffffffu, sum_hi, 2);
            l_lo = l_lo * a_lo + sum_lo;
            l_hi = l_hi * a_hi + sum_hi;
            m_lo = mn_lo; m_hi = mn_hi;
            __syncwarp();                      // P visible within warp

            // ---- O += P V_sub ----
            #pragma unroll
            for (int kk = 0; kk < 4; kk++) {
                unsigned pa[4];
                ldsm_x4(pa[0], pa[1], pa[2], pa[3],
                        p_base + 2 * (r0 * AT + kk * 16 + xl));
                #pragma unroll
                for (int nfp = 0; nfp < 4; nfp++) {
                    unsigned v0, v1, v2, v3;
                    ldsm_x4t(v0, v1, v2, v3,
                             v_base + 2 * ((so + kk * 16 + (lane & 15)) * AT + nfp * 16 + (lane >> 4) * 8));
                    mma_f16(o[2 * nfp],     pa, v0, v1);
                    mma_f16(o[2 * nfp + 1], pa, v2, v3);
                }
            }
        }
        __syncthreads();                       // all warps done with K/V before overwrite
    }

    float inv_lo = 1.f / l_lo;
    float inv_hi = 1.f / l_hi;
    const int qrow_lo = blockIdx.x * 128 + r0 + g;
    __half* out_lo = g_ah + ((size_t)b * Ssz + qrow_lo) * Esz + h * Dsz;
    __half* out_hi = out_lo + 8 * Esz;
    #pragma unroll
    for (int nf = 0; nf < 8; nf++) {
        int col = nf * 8 + 2 * tg;
        *(__half2*)(out_lo + col) = __floats2half2_rn(o[nf][0] * inv_lo, o[nf][1] * inv_lo);
        *(__half2*)(out_hi + col) = __floats2half2_rn(o[nf][2] * inv_hi, o[nf][3] * inv_hi);
    }
}

// ---------------- launch ----------------
extern "C" void kernel_launch(void* const* d_in, const int* in_sizes, int n_in,
                              void* d_out, int out_size)
{
    const float* X  = (const float*)d_in[0];
    const float* Wq = (const float*)d_in[1];
    const float* bq = (const float*)d_in[2];
    const float* Wk = (const float*)d_in[3];
    const float* bk = (const float*)d_in[4];
    const float* Wv = (const float*)d_in[5];
    const float* bv = (const float*)d_in[6];
    const float* Wo = (const float*)d_in[7];
    const float* bo = (const float*)d_in[8];
    float* out = (float*)d_out;

    (void)cudaFuncSetAttribute(gemm_h, cudaFuncAttributeMaxDynamicSharedMemorySize, GSMEM);
    (void)cudaFuncSetAttribute(attn_kernel, cudaFuncAttributeMaxDynamicSharedMemorySize, ATTN_SMEM);

    // one-time fp16 conversions
    conv_x<<<(Msz * Esz) / (256 * 8), 256>>>(X);
    conv_wqkvT<<<3 * Esz, 128>>>(Wq, Wk, Wv);
    conv_woT<<<Esz, 128>>>(Wo);

    // QKV projection (fp16 mma + cp.async 3-stage, Kc=64)
    gemm_h<<<dim3(18, 64), 256, GSMEM>>>(bq, bk, bv, nullptr, 0);

    // attention (Br=128, 128 keys per barrier round)
    attn_kernel<<<dim3(Ssz / 128, Bsz * Hsz), 256, ATTN_SMEM>>>();

    // output projection
    gemm_h<<<dim3(6, 64), 256, GSMEM>>>(bo, nullptr, nullptr, out, 1);
}

// round 16
// speedup vs baseline: 1.3994x; 1.0459x over previous
#include <cuda_runtime.h>
#include <cuda_fp16.h>
#include <cstdint>

#define Bsz 8
#define Ssz 1024
#define Esz 768
#define Hsz 12
#define Dsz 64
#define Msz (Bsz*Ssz)   // 8192

// ---------------- scratch (device globals; referenced ONLY in device code) ----------------
__device__ __half g_qh[Bsz*Hsz*Ssz*Dsz];    // fp16 q (pre-scaled 0.125)
__device__ __half g_kh[Bsz*Hsz*Ssz*Dsz];    // fp16 k
__device__ __half g_vh[Bsz*Hsz*Ssz*Dsz];    // fp16 v
__device__ __half g_ah[(size_t)Msz*Esz];    // fp16 attention output [B*S][E]
__device__ __half g_xh[(size_t)Msz*Esz];    // fp16 X
__device__ __half g_wTh[(size_t)(3*Esz)*Esz]; // fp16 W^T [2304][768], q rows pre-scaled
__device__ __half g_woTh[(size_t)Esz*Esz];  // fp16 Wo^T [768][768]

// ---------------- helpers ----------------
__device__ __forceinline__ void mma_f16(float* c, const unsigned* a, unsigned b0, unsigned b1) {
    asm volatile(
        "mma.sync.aligned.m16n8k16.row.col.f32.f16.f16.f32 "
        "{%0,%1,%2,%3}, {%4,%5,%6,%7}, {%8,%9}, {%0,%1,%2,%3};"
        : "+f"(c[0]), "+f"(c[1]), "+f"(c[2]), "+f"(c[3])
        : "r"(a[0]), "r"(a[1]), "r"(a[2]), "r"(a[3]), "r"(b0), "r"(b1));
}
__device__ __forceinline__ void ldsm_x4(unsigned& r0, unsigned& r1, unsigned& r2, unsigned& r3,
                                        unsigned saddr) {
    asm volatile("ldmatrix.sync.aligned.m8n8.x4.shared.b16 {%0,%1,%2,%3}, [%4];"
        : "=r"(r0), "=r"(r1), "=r"(r2), "=r"(r3) : "r"(saddr));
}
__device__ __forceinline__ void ldsm_x4t(unsigned& r0, unsigned& r1, unsigned& r2, unsigned& r3,
                                         unsigned saddr) {
    asm volatile("ldmatrix.sync.aligned.m8n8.x4.trans.shared.b16 {%0,%1,%2,%3}, [%4];"
        : "=r"(r0), "=r"(r1), "=r"(r2), "=r"(r3) : "r"(saddr));
}
__device__ __forceinline__ unsigned smem_u32(const void* p) {
    unsigned a;
    asm("{ .reg .u64 t; cvta.to.shared.u64 t, %1; cvt.u32.u64 %0, t; }" : "=r"(a) : "l"(p));
    return a;
}
__device__ __forceinline__ void cp16(unsigned dst, const void* src) {
    asm volatile("cp.async.cg.shared.global [%0], [%1], 16;" :: "r"(dst), "l"(src));
}
#define CP_COMMIT()  asm volatile("cp.async.commit_group;" ::: "memory")
#define CP_WAIT1()   asm volatile("cp.async.wait_group 1;" ::: "memory")
__device__ __forceinline__ unsigned pack_h2(float a, float b) {
    __half2 h = __floats2half2_rn(a, b);
    return *(unsigned*)&h;
}

// ============================================================================
// Conversion kernels (one-time). fp32 -> fp16.
// ============================================================================
__global__ __launch_bounds__(256) void conv_x(const float* __restrict__ src)
{
    int i = (blockIdx.x * 256 + threadIdx.x) * 8;
    float4 a = *(const float4*)(src + i);
    float4 b = *(const float4*)(src + i + 4);
    __align__(16) __half h[8];
    h[0] = __float2half_rn(a.x); h[1] = __float2half_rn(a.y);
    h[2] = __float2half_rn(a.z); h[3] = __float2half_rn(a.w);
    h[4] = __float2half_rn(b.x); h[5] = __float2half_rn(b.y);
    h[6] = __float2half_rn(b.z); h[7] = __float2half_rn(b.w);
    *(uint4*)(g_xh + i) = *(uint4*)h;
}

__global__ __launch_bounds__(128) void conv_wqkvT(const float* __restrict__ Wq,
                                                  const float* __restrict__ Wk,
                                                  const float* __restrict__ Wv)
{
    int n = blockIdx.x;
    int which = n / Esz, rem = n % Esz, h = rem >> 6, d = rem & 63;
    const float* W = (which == 0) ? Wq : (which == 1 ? Wk : Wv);
    const float sc = (which == 0) ? 0.125f : 1.0f;
    const float* col = W + (size_t)h * Esz * Dsz + d;
    __half* row = g_wTh + (size_t)n * Esz;
    for (int e = threadIdx.x; e < Esz; e += 128)
        row[e] = __float2half_rn(col[(size_t)e * Dsz] * sc);
}

__global__ __launch_bounds__(128) void conv_woT(const float* __restrict__ Wo)
{
    int n = blockIdx.x;
    __half* row = g_woTh + (size_t)n * Esz;
    for (int e = threadIdx.x; e < Esz; e += 128)
        row[e] = __float2half_rn(Wo[(size_t)e * Esz + n]);
}

// ============================================================================
// fp16 GEMM, 3-stage cp.async pipeline, Kc=64 — UNCHANGED from R14/R15 (proven).
// ============================================================================
#define GST 72
#define STG_BYTES (128*GST*2*2)           // 36864
#define AOFFB (128*GST*2)                 // 18432
#define GSMEM (3*STG_BYTES)               // 110592
#define CHUNKS 12

__global__ __launch_bounds__(256, 2) void gemm_h(
    const float* __restrict__ b0p, const float* __restrict__ b1p,
    const float* __restrict__ b2p,
    float* __restrict__ Out, int mode)
{
    extern __shared__ __align__(16) char smem[];
    const unsigned sbase = smem_u32(smem);

    const __half* A  = (mode == 0) ? g_xh  : g_ah;
    const __half* Bt = (mode == 0) ? g_wTh : g_woTh;

    const int t    = threadIdx.x;
    const int warp = t >> 5;
    const int lane = t & 31;
    const int g    = lane >> 2;
    const int tg   = lane & 3;
    const int wm   = (warp & 1) * 64;
    const int wn   = (warp >> 1) * 32;
    const int n0   = blockIdx.x * 128;
    const int m0   = blockIdx.y * 128;

    const unsigned xl = (lane & 15) * GST + (lane >> 4) * 8;

    const int row_ = t >> 1;
    const int sb_  = (t & 1) * 4;
    const __half* Ag = A  + (size_t)(m0 + row_) * Esz;
    const __half* Bg = Bt + (size_t)(n0 + row_) * Esz;

#define GISSUE(chunk, buf) do {                                               \
    const unsigned s0 = sbase + (unsigned)(buf) * STG_BYTES;                  \
    const int c0 = (chunk) * 64;                                              \
    _Pragma("unroll")                                                         \
    for (int it = 0; it < 4; it++) {                                          \
        const int seg = sb_ + it;                                             \
        cp16(s0 + (unsigned)(row_ * GST + seg * 8) * 2, Ag + c0 + seg * 8);   \
        cp16(s0 + AOFFB + (unsigned)(row_ * GST + seg * 8) * 2, Bg + c0 + seg * 8); \
    }                                                                         \
} while (0)

    GISSUE(0, 0); CP_COMMIT();
    GISSUE(1, 1); CP_COMMIT();

    float acc[4][4][4];
    #pragma unroll
    for (int mi = 0; mi < 4; mi++)
        #pragma unroll
        for (int ni = 0; ni < 4; ni++)
            #pragma unroll
            for (int j = 0; j < 4; j++) acc[mi][ni][j] = 0.f;

    int buf = 0, buf2 = 2;
    for (int i = 0; i < CHUNKS; i++) {
        CP_WAIT1();
        __syncthreads();
        if (i + 2 < CHUNKS) GISSUE(i + 2, buf2);
        CP_COMMIT();

        const unsigned sA = sbase + (unsigned)buf * STG_BYTES;
        const unsigned sB = sA + AOFFB;

        #pragma unroll
        for (int ks = 0; ks < 4; ks++) {
            unsigned bfr[2][4];
            #pragma unroll
            for (int nip = 0; nip < 2; nip++)
                ldsm_x4(bfr[nip][0], bfr[nip][1], bfr[nip][2], bfr[nip][3],
                        sB + 2 * ((wn + nip * 16) * GST + ks * 16 + xl));
            unsigned a[4][4];
            #pragma unroll
            for (int mi = 0; mi < 4; mi++)
                ldsm_x4(a[mi][0], a[mi][1], a[mi][2], a[mi][3],
                        sA + 2 * ((wm + mi * 16) * GST + ks * 16 + xl));
            #pragma unroll
            for (int nip = 0; nip < 2; nip++)
                #pragma unroll
                for (int mi = 0; mi < 4; mi++) {
                    mma_f16(acc[mi][2 * nip],     a[mi], bfr[nip][0], bfr[nip][2]);
                    mma_f16(acc[mi][2 * nip + 1], a[mi], bfr[nip][1], bfr[nip][3]);
                }
        }
        buf  = (buf  == 2) ? 0 : buf + 1;
        buf2 = (buf2 == 2) ? 0 : buf2 + 1;
    }
#undef GISSUE

    if (mode == 0) {
        const int which = n0 / Esz;
        const float* bias = (which == 0) ? b0p : (which == 1 ? b1p : b2p);
        __half* OUTsel    = (which == 0) ? g_qh : (which == 1 ? g_kh : g_vh);
        const float bsc   = (which == 0) ? 0.125f : 1.0f;
        const int nrel = n0 % Esz;
        #pragma unroll
        for (int mi = 0; mi < 4; mi++) {
            const int row_lo = m0 + wm + mi * 16 + g;
            const int row_hi = row_lo + 8;
            const int blo = row_lo >> 10, slo = row_lo & 1023;
            const int bhi = row_hi >> 10, shi = row_hi & 1023;
            #pragma unroll
            for (int ni = 0; ni < 4; ni++) {
                const int nc = nrel + wn + ni * 8 + 2 * tg;
                const int head = nc >> 6, d = nc & 63;
                float2 bb = *(const float2*)(bias + head * Dsz + d);
                bb.x *= bsc; bb.y *= bsc;
                __half* olo = OUTsel + ((((size_t)blo * Hsz + head) << 10) + slo) * Dsz + d;
                __half* ohi = OUTsel + ((((size_t)bhi * Hsz + head) << 10) + shi) * Dsz + d;
                *(__half2*)olo = __floats2half2_rn(acc[mi][ni][0] + bb.x, acc[mi][ni][1] + bb.y);
                *(__half2*)ohi = __floats2half2_rn(acc[mi][ni][2] + bb.x, acc[mi][ni][3] + bb.y);
            }
        }
    } else {
        #pragma unroll
        for (int mi = 0; mi < 4; mi++) {
            const int row_lo = m0 + wm + mi * 16 + g;
            float* olo = Out + (size_t)row_lo * Esz + n0;
            float* ohi = olo + (size_t)8 * Esz;
            #pragma unroll
            for (int ni = 0; ni < 4; ni++) {
                const int col = wn + ni * 8 + 2 * tg;
                float2 bb = *(const float2*)(b0p + n0 + col);
                float2 wlo, whi;
                wlo.x = acc[mi][ni][0] + bb.x; wlo.y = acc[mi][ni][1] + bb.y;
                whi.x = acc[mi][ni][2] + bb.x; whi.y = acc[mi][ni][3] + bb.y;
                *(float2*)(olo + col) = wlo;
                *(float2*)(ohi + col) = whi;
            }
        }
    }
}

// ============================================================================
// Flash attention fp16, Br=128, 8 warps. P kept entirely in REGISTERS
// (S-fragment == P A-fragment layout), no P smem buffer. 256 keys per barrier
// round (4 rounds, 2 barriers each), processed as four 64-key subtiles.
// Dynamic smem (halves): K[256][72] | V[256][72] = 73728 B.
// ============================================================================
#define AT 72
#define K_OFF 0
#define V_OFF (256*AT)
#define ATTN_SMEM (512*AT*2)   // 73728

__global__ __launch_bounds__(256) void attn_kernel()
{
    extern __shared__ __align__(16) __half hsm[];
    __half* Ksm = hsm + K_OFF;
    __half* Vsm = hsm + V_OFF;

    const int bh = blockIdx.y;
    const int b = bh / Hsz, h = bh % Hsz;
    const int tid  = threadIdx.x;
    const int warp = tid >> 5;
    const int lane = tid & 31;
    const int g  = lane >> 2;
    const int tg = lane & 3;
    const int r0 = warp * 16;

    const unsigned k_base = smem_u32(Ksm);
    const unsigned v_base = smem_u32(Vsm);
    const unsigned xl = (lane & 15) * AT + (lane >> 4) * 8;

    // ---- stage Q (scaled fp16) rows 0-127 into K buffer, extract A-frags ----
    {
        const uint4* Qg = (const uint4*)(g_qh + ((size_t)bh * Ssz + blockIdx.x * 128) * Dsz);
        #pragma unroll
        for (int i = 0; i < 4; i++) {
            int idx = i * 256 + tid;
            int row = idx >> 3, c = (idx & 7) * 8;
            *(uint4*)&Ksm[row * AT + c] = Qg[idx];
        }
    }
    __syncthreads();

    unsigned qa[4][4];
    #pragma unroll
    for (int kk = 0; kk < 4; kk++)
        ldsm_x4(qa[kk][0], qa[kk][1], qa[kk][2], qa[kk][3],
                k_base + 2 * (r0 * AT + kk * 16 + xl));
    __syncthreads();                        // Q extracted; K buffer free

    float o[8][4];
    #pragma unroll
    for (int nf = 0; nf < 8; nf++)
        #pragma unroll
        for (int j = 0; j < 4; j++) o[nf][j] = 0.f;
    float m_lo = -1e30f, m_hi = -1e30f, l_lo = 0.f, l_hi = 0.f;

    const uint4* Kg0 = (const uint4*)(g_kh + (size_t)bh * (Ssz * Dsz));
    const uint4* Vg0 = (const uint4*)(g_vh + (size_t)bh * (Ssz * Dsz));

    for (int kb = 0; kb < Ssz / 256; kb++) {   // 4 rounds of 256 keys
        const uint4* Kg = Kg0 + kb * 2048;     // 256 rows * 64 halves / 8
        const uint4* Vg = Vg0 + kb * 2048;
        #pragma unroll
        for (int i = 0; i < 8; i++) {
            int idx = i * 256 + tid;
            int row = idx >> 3, c = (idx & 7) * 8;
            *(uint4*)&Ksm[row * AT + c] = Kg[idx];
            *(uint4*)&Vsm[row * AT + c] = Vg[idx];
        }
        __syncthreads();

        #pragma unroll
        for (int sub = 0; sub < 4; sub++) {
            const int so = sub * 64;           // subtile key offset

            // ---- S = Q K_sub^T ----
            float s[8][4];
            #pragma unroll
            for (int nf = 0; nf < 8; nf++)
                #pragma unroll
                for (int j = 0; j < 4; j++) s[nf][j] = 0.f;

            #pragma unroll
            for (int nfp = 0; nfp < 4; nfp++) {
                #pragma unroll
                for (int kk = 0; kk < 4; kk++) {
                    unsigned kb0, kb1, kb2, kb3;
                    ldsm_x4(kb0, kb1, kb2, kb3,
                            k_base + 2 * ((so + nfp * 16) * AT + kk * 16 + xl));
                    mma_f16(s[2 * nfp],     qa[kk], kb0, kb2);
                    mma_f16(s[2 * nfp + 1], qa[kk], kb1, kb3);
                }
            }

            // ---- online softmax ----
            float tmax_lo = -1e30f, tmax_hi = -1e30f;
            #pragma unroll
            for (int nf = 0; nf < 8; nf++) {
                tmax_lo = fmaxf(tmax_lo, fmaxf(s[nf][0], s[nf][1]));
                tmax_hi = fmaxf(tmax_hi, fmaxf(s[nf][2], s[nf][3]));
            }
            tmax_lo = fmaxf(tmax_lo, __shfl_xor_sync(0xffffffffu, tmax_lo, 1));
            tmax_lo = fmaxf(tmax_lo, __shfl_xor_sync(0xffffffffu, tmax_lo, 2));
            tmax_hi = fmaxf(tmax_hi, __shfl_xor_sync(0xffffffffu, tmax_hi, 1));
            tmax_hi = fmaxf(tmax_hi, __shfl_xor_sync(0xffffffffu, tmax_hi, 2));

            float mn_lo = fmaxf(m_lo, tmax_lo);
            float mn_hi = fmaxf(m_hi, tmax_hi);
            float a_lo = __expf(m_lo - mn_lo);
            float a_hi = __expf(m_hi - mn_hi);

            // ---- exp + pack P directly into A-fragments (registers only) ----
            unsigned pa[4][4];
            float sum_lo = 0.f, sum_hi = 0.f;
            #pragma unroll
            for (int nf = 0; nf < 8; nf++) {
                float p0 = __expf(s[nf][0] - mn_lo);
                float p1 = __expf(s[nf][1] - mn_lo);
                float p2 = __expf(s[nf][2] - mn_hi);
                float p3 = __expf(s[nf][3] - mn_hi);
                sum_lo += p0 + p1;
                sum_hi += p2 + p3;
                const int kk = nf >> 1;
                const int half = (nf & 1) << 1;        // 0 or 2
                pa[kk][half]     = pack_h2(p0, p1);    // rows g
                pa[kk][half + 1] = pack_h2(p2, p3);    // rows g+8
                o[nf][0] *= a_lo; o[nf][1] *= a_lo;
                o[nf][2] *= a_hi; o[nf][3] *= a_hi;
            }
            // NB: pa[kk] = {rowg k0-7, rowg+8 k0-7, rowg k8-15, rowg+8 k8-15}
            // matches m16n8k16 A layout: a0=(g,2tg..), a1=(g+8,..), a2=(g,8+2tg..), a3=(g+8,..)
            sum_lo += __shfl_xor_sync(0xffffffffu, sum_lo, 1);
            sum_lo += __shfl_xor_sync(0xffffffffu, sum_lo, 2);
            sum_hi += __shfl_xor_sync(0xffffffffu, sum_hi, 1);
            sum_hi += __shfl_xor_sync(0xffffffffu, sum_hi, 2);
            l_lo = l_lo * a_lo + sum_lo;
            l_hi = l_hi * a_hi + sum_hi;
            m_lo = mn_lo; m_hi = mn_hi;

            // fix fragment order: a1 must be row g+8 cols 0-7 = pack(p2,p3) of even nf;
            // a2 must be row g cols 8-15 = pack(p0,p1) of odd nf. Swap middle two.
            #pragma unroll
            for (int kk = 0; kk < 4; kk++) {
                unsigned tmp = pa[kk][1];
                pa[kk][1] = pa[kk][1]; // placeholder (see note)
                tmp = tmp;
            }
            // Correct mapping already achieved: for even nf (=2kk): half=0 -> pa[kk][0]=(g,k0-7)=a0,
            // pa[kk][1]=(g+8,k0-7)=a1. For odd nf: half=2 -> pa[kk][2]=(g,k8-15)=a2, pa[kk][3]=(g+8)=a3. OK.

            // ---- O += P V_sub (V via ldsm.trans) ----
            #pragma unroll
            for (int kk = 0; kk < 4; kk++) {
                #pragma unroll
                for (int nfp = 0; nfp < 4; nfp++) {
                    unsigned v0, v1, v2, v3;
                    ldsm_x4t(v0, v1, v2, v3,
                             v_base + 2 * ((so + kk * 16 + (lane & 15)) * AT + nfp * 16 + (lane >> 4) * 8));
                    mma_f16(o[2 * nfp],     pa[kk], v0, v1);
                    mma_f16(o[2 * nfp + 1], pa[kk], v2, v3);
                }
            }
        }
        __syncthreads();                       // all warps done with K/V before overwrite
    }

    float inv_lo = 1.f / l_lo;
    float inv_hi = 1.f / l_hi;
    const int qrow_lo = blockIdx.x * 128 + r0 + g;
    __half* out_lo = g_ah + ((size_t)b * Ssz + qrow_lo) * Esz + h * Dsz;
    __half* out_hi = out_lo + 8 * Esz;
    #pragma unroll
    for (int nf = 0; nf < 8; nf++) {
        int col = nf * 8 + 2 * tg;
        *(__half2*)(out_lo + col) = __floats2half2_rn(o[nf][0] * inv_lo, o[nf][1] * inv_lo);
        *(__half2*)(out_hi + col) = __floats2half2_rn(o[nf][2] * inv_hi, o[nf][3] * inv_hi);
    }
}

// ---------------- launch ----------------
extern "C" void kernel_launch(void* const* d_in, const int* in_sizes, int n_in,
                              void* d_out, int out_size)
{
    const float* X  = (const float*)d_in[0];
    const float* Wq = (const float*)d_in[1];
    const float* bq = (const float*)d_in[2];
    const float* Wk = (const float*)d_in[3];
    const float* bk = (const float*)d_in[4];
    const float* Wv = (const float*)d_in[5];
    const float* bv = (const float*)d_in[6];
    const float* Wo = (const float*)d_in[7];
    const float* bo = (const float*)d_in[8];
    float* out = (float*)d_out;

    (void)cudaFuncSetAttribute(gemm_h, cudaFuncAttributeMaxDynamicSharedMemorySize, GSMEM);
    (void)cudaFuncSetAttribute(attn_kernel, cudaFuncAttributeMaxDynamicSharedMemorySize, ATTN_SMEM);

    // one-time fp16 conversions
    conv_x<<<(Msz * Esz) / (256 * 8), 256>>>(X);
    conv_wqkvT<<<3 * Esz, 128>>>(Wq, Wk, Wv);
    conv_woT<<<Esz, 128>>>(Wo);

    // QKV projection (fp16 mma + cp.async 3-stage, Kc=64)
    gemm_h<<<dim3(18, 64), 256, GSMEM>>>(bq, bk, bv, nullptr, 0);

    // attention (Br=128, 256 keys per barrier round, register-resident P)
    attn_kernel<<<dim3(Ssz / 128, Bsz * Hsz), 256, ATTN_SMEM>>>();

    // output projection
    gemm_h<<<dim3(6, 64), 256, GSMEM>>>(bo, nullptr, nullptr, out, 1);
}

// round 17
// speedup vs baseline: 1.5416x; 1.1017x over previous
#include <cuda_runtime.h>
#include <cuda_fp16.h>
#include <cstdint>

#define Bsz 8
#define Ssz 1024
#define Esz 768
#define Hsz 12
#define Dsz 64
#define Msz (Bsz*Ssz)   // 8192

// ---------------- scratch (device globals; referenced ONLY in device code) ----------------
__device__ __half g_qh[Bsz*Hsz*Ssz*Dsz];    // fp16 q (pre-scaled 0.125)
__device__ __half g_kh[Bsz*Hsz*Ssz*Dsz];    // fp16 k
__device__ __half g_vh[Bsz*Hsz*Ssz*Dsz];    // fp16 v
__device__ __half g_ah[(size_t)Msz*Esz];    // fp16 attention output [B*S][E]
__device__ __half g_xh[(size_t)Msz*Esz];    // fp16 X
__device__ __half g_wTh[(size_t)(3*Esz)*Esz]; // fp16 W^T [2304][768], q rows pre-scaled
__device__ __half g_woTh[(size_t)Esz*Esz];  // fp16 Wo^T [768][768]

// ---------------- helpers ----------------
__device__ __forceinline__ void mma_f16(float* c, const unsigned* a, unsigned b0, unsigned b1) {
    asm volatile(
        "mma.sync.aligned.m16n8k16.row.col.f32.f16.f16.f32 "
        "{%0,%1,%2,%3}, {%4,%5,%6,%7}, {%8,%9}, {%0,%1,%2,%3};"
        : "+f"(c[0]), "+f"(c[1]), "+f"(c[2]), "+f"(c[3])
        : "r"(a[0]), "r"(a[1]), "r"(a[2]), "r"(a[3]), "r"(b0), "r"(b1));
}
__device__ __forceinline__ void ldsm_x4(unsigned& r0, unsigned& r1, unsigned& r2, unsigned& r3,
                                        unsigned saddr) {
    asm volatile("ldmatrix.sync.aligned.m8n8.x4.shared.b16 {%0,%1,%2,%3}, [%4];"
        : "=r"(r0), "=r"(r1), "=r"(r2), "=r"(r3) : "r"(saddr));
}
__device__ __forceinline__ void ldsm_x4t(unsigned& r0, unsigned& r1, unsigned& r2, unsigned& r3,
                                         unsigned saddr) {
    asm volatile("ldmatrix.sync.aligned.m8n8.x4.trans.shared.b16 {%0,%1,%2,%3}, [%4];"
        : "=r"(r0), "=r"(r1), "=r"(r2), "=r"(r3) : "r"(saddr));
}
__device__ __forceinline__ unsigned smem_u32(const void* p) {
    unsigned a;
    asm("{ .reg .u64 t; cvta.to.shared.u64 t, %1; cvt.u32.u64 %0, t; }" : "=r"(a) : "l"(p));
    return a;
}
__device__ __forceinline__ void cp16(unsigned dst, const void* src) {
    asm volatile("cp.async.cg.shared.global [%0], [%1], 16;" :: "r"(dst), "l"(src));
}
#define CP_COMMIT()  asm volatile("cp.async.commit_group;" ::: "memory")
#define CP_WAIT1()   asm volatile("cp.async.wait_group 1;" ::: "memory")
__device__ __forceinline__ unsigned pack_h2(float a, float b) {
    __half2 h = __floats2half2_rn(a, b);
    return *(unsigned*)&h;
}

// ============================================================================
// Conversion kernels (one-time). fp32 -> fp16.
// ============================================================================
__global__ __launch_bounds__(256) void conv_x(const float* __restrict__ src)
{
    int i = (blockIdx.x * 256 + threadIdx.x) * 8;
    float4 a = *(const float4*)(src + i);
    float4 b = *(const float4*)(src + i + 4);
    __align__(16) __half h[8];
    h[0] = __float2half_rn(a.x); h[1] = __float2half_rn(a.y);
    h[2] = __float2half_rn(a.z); h[3] = __float2half_rn(a.w);
    h[4] = __float2half_rn(b.x); h[5] = __float2half_rn(b.y);
    h[6] = __float2half_rn(b.z); h[7] = __float2half_rn(b.w);
    *(uint4*)(g_xh + i) = *(uint4*)h;
}

__global__ __launch_bounds__(128) void conv_wqkvT(const float* __restrict__ Wq,
                                                  const float* __restrict__ Wk,
                                                  const float* __restrict__ Wv)
{
    int n = blockIdx.x;
    int which = n / Esz, rem = n % Esz, h = rem >> 6, d = rem & 63;
    const float* W = (which == 0) ? Wq : (which == 1 ? Wk : Wv);
    const float sc = (which == 0) ? 0.125f : 1.0f;
    const float* col = W + (size_t)h * Esz * Dsz + d;
    __half* row = g_wTh + (size_t)n * Esz;
    for (int e = threadIdx.x; e < Esz; e += 128)
        row[e] = __float2half_rn(col[(size_t)e * Dsz] * sc);
}

__global__ __launch_bounds__(128) void conv_woT(const float* __restrict__ Wo)
{
    int n = blockIdx.x;
    __half* row = g_woTh + (size_t)n * Esz;
    for (int e = threadIdx.x; e < Esz; e += 128)
        row[e] = __float2half_rn(Wo[(size_t)e * Esz + n]);
}

// ============================================================================
// fp16 GEMM, 3-stage cp.async pipeline, Kc=64. Tile 256M x 128N, 512 threads
// (16 warps, 4m x 4n, warp tile 64x32 — inner loop identical to R14-proven).
//   mode 0: A=g_xh, Bt=g_wTh -> qkv (per-head bias, fp16 scatter to g_qh/kh/vh)
//   mode 1: A=g_ah, Bt=g_woTh -> oproj (bias bo, fp32 row-major Out)
// ============================================================================
#define GST 72
#define ASTAGE (256*GST*2)                // 36864 B
#define BSTAGE (128*GST*2)                // 18432 B
#define STG_BYTES (ASTAGE + BSTAGE)       // 55296 B
#define GSMEM (3*STG_BYTES)               // 165888 B
#define CHUNKS 12

__global__ __launch_bounds__(512, 1) void gemm_h(
    const float* __restrict__ b0p, const float* __restrict__ b1p,
    const float* __restrict__ b2p,
    float* __restrict__ Out, int mode)
{
    extern __shared__ __align__(16) char smem[];
    const unsigned sbase = smem_u32(smem);

    const __half* A  = (mode == 0) ? g_xh  : g_ah;
    const __half* Bt = (mode == 0) ? g_wTh : g_woTh;

    const int t    = threadIdx.x;
    const int warp = t >> 5;
    const int lane = t & 31;
    const int g    = lane >> 2;
    const int tg   = lane & 3;
    const int wm   = (warp & 3) * 64;      // 0..192
    const int wn   = (warp >> 2) * 32;     // 0..96
    const int n0   = blockIdx.x * 128;
    const int m0   = blockIdx.y * 256;

    const unsigned xl = (lane & 15) * GST + (lane >> 4) * 8;

    const __half* Ag = A  + (size_t)m0 * Esz;
    const __half* Bg = Bt + (size_t)n0 * Esz;

#define GISSUE(chunk, buf) do {                                               \
    const unsigned s0 = sbase + (unsigned)(buf) * STG_BYTES;                  \
    const int c0 = (chunk) * 64;                                              \
    _Pragma("unroll")                                                         \
    for (int it = 0; it < 4; it++) {       /* A: 2048 lines */                \
        const int idx = it * 512 + t;                                         \
        const int row = idx >> 3, seg = idx & 7;                              \
        cp16(s0 + (unsigned)(row * GST + seg * 8) * 2,                        \
             Ag + (size_t)row * Esz + c0 + seg * 8);                          \
    }                                                                         \
    _Pragma("unroll")                                                         \
    for (int it = 0; it < 2; it++) {       /* B: 1024 lines */                \
        const int idx = it * 512 + t;                                         \
        const int row = idx >> 3, seg = idx & 7;                              \
        cp16(s0 + ASTAGE + (unsigned)(row * GST + seg * 8) * 2,               \
             Bg + (size_t)row * Esz + c0 + seg * 8);                          \
    }                                                                         \
} while (0)

    GISSUE(0, 0); CP_COMMIT();
    GISSUE(1, 1); CP_COMMIT();

    float acc[4][4][4];
    #pragma unroll
    for (int mi = 0; mi < 4; mi++)
        #pragma unroll
        for (int ni = 0; ni < 4; ni++)
            #pragma unroll
            for (int j = 0; j < 4; j++) acc[mi][ni][j] = 0.f;

    int buf = 0, buf2 = 2;
    for (int i = 0; i < CHUNKS; i++) {
        CP_WAIT1();
        __syncthreads();
        if (i + 2 < CHUNKS) GISSUE(i + 2, buf2);
        CP_COMMIT();

        const unsigned sA = sbase + (unsigned)buf * STG_BYTES;
        const unsigned sB = sA + ASTAGE;

        #pragma unroll
        for (int ks = 0; ks < 4; ks++) {
            unsigned bfr[2][4];
            #pragma unroll
            for (int nip = 0; nip < 2; nip++)
                ldsm_x4(bfr[nip][0], bfr[nip][1], bfr[nip][2], bfr[nip][3],
                        sB + 2 * ((wn + nip * 16) * GST + ks * 16 + xl));
            unsigned a[4][4];
            #pragma unroll
            for (int mi = 0; mi < 4; mi++)
                ldsm_x4(a[mi][0], a[mi][1], a[mi][2], a[mi][3],
                        sA + 2 * ((wm + mi * 16) * GST + ks * 16 + xl));
            #pragma unroll
            for (int nip = 0; nip < 2; nip++)
                #pragma unroll
                for (int mi = 0; mi < 4; mi++) {
                    mma_f16(acc[mi][2 * nip],     a[mi], bfr[nip][0], bfr[nip][2]);
                    mma_f16(acc[mi][2 * nip + 1], a[mi], bfr[nip][1], bfr[nip][3]);
                }
        }
        buf  = (buf  == 2) ? 0 : buf + 1;
        buf2 = (buf2 == 2) ? 0 : buf2 + 1;
    }
#undef GISSUE

    if (mode == 0) {
        const int which = n0 / Esz;
        const float* bias = (which == 0) ? b0p : (which == 1 ? b1p : b2p);
        __half* OUTsel    = (which == 0) ? g_qh : (which == 1 ? g_kh : g_vh);
        const float bsc   = (which == 0) ? 0.125f : 1.0f;
        const int nrel = n0 % Esz;
        #pragma unroll
        for (int mi = 0; mi < 4; mi++) {
            const int row_lo = m0 + wm + mi * 16 + g;
            const int row_hi = row_lo + 8;
            const int blo = row_lo >> 10, slo = row_lo & 1023;
            const int bhi = row_hi >> 10, shi = row_hi & 1023;
            #pragma unroll
            for (int ni = 0; ni < 4; ni++) {
                const int nc = nrel + wn + ni * 8 + 2 * tg;
                const int head = nc >> 6, d = nc & 63;
                float2 bb = *(const float2*)(bias + head * Dsz + d);
                bb.x *= bsc; bb.y *= bsc;
                __half* olo = OUTsel + ((((size_t)blo * Hsz + head) << 10) + slo) * Dsz + d;
                __half* ohi = OUTsel + ((((size_t)bhi * Hsz + head) << 10) + shi) * Dsz + d;
                *(__half2*)olo = __floats2half2_rn(acc[mi][ni][0] + bb.x, acc[mi][ni][1] + bb.y);
                *(__half2*)ohi = __floats2half2_rn(acc[mi][ni][2] + bb.x, acc[mi][ni][3] + bb.y);
            }
        }
    } else {
        #pragma unroll
        for (int mi = 0; mi < 4; mi++) {
            const int row_lo = m0 + wm + mi * 16 + g;
            float* olo = Out + (size_t)row_lo * Esz + n0;
            float* ohi = olo + (size_t)8 * Esz;
            #pragma unroll
            for (int ni = 0; ni < 4; ni++) {
                const int col = wn + ni * 8 + 2 * tg;
                float2 bb = *(const float2*)(b0p + n0 + col);
                float2 wlo, whi;
                wlo.x = acc[mi][ni][0] + bb.x; wlo.y = acc[mi][ni][1] + bb.y;
                whi.x = acc[mi][ni][2] + bb.x; whi.y = acc[mi][ni][3] + bb.y;
                *(float2*)(olo + col) = wlo;
                *(float2*)(ohi + col) = whi;
            }
        }
    }
}

// ============================================================================
// Flash attention fp16 — UNCHANGED from R16 (proven): Br=128, register P,
// 256 keys per barrier round. Dead placeholder loop removed.
// ============================================================================
#define AT 72
#define K_OFF 0
#define V_OFF (256*AT)
#define ATTN_SMEM (512*AT*2)   // 73728

__global__ __launch_bounds__(256) void attn_kernel()
{
    extern __shared__ __align__(16) __half hsm[];
    __half* Ksm = hsm + K_OFF;
    __half* Vsm = hsm + V_OFF;

    const int bh = blockIdx.y;
    const int b = bh / Hsz, h = bh % Hsz;
    const int tid  = threadIdx.x;
    const int warp = tid >> 5;
    const int lane = tid & 31;
    const int g  = lane >> 2;
    const int tg = lane & 3;
    const int r0 = warp * 16;

    const unsigned k_base = smem_u32(Ksm);
    const unsigned v_base = smem_u32(Vsm);
    const unsigned xl = (lane & 15) * AT + (lane >> 4) * 8;

    {
        const uint4* Qg = (const uint4*)(g_qh + ((size_t)bh * Ssz + blockIdx.x * 128) * Dsz);
        #pragma unroll
        for (int i = 0; i < 4; i++) {
            int idx = i * 256 + tid;
            int row = idx >> 3, c = (idx & 7) * 8;
            *(uint4*)&Ksm[row * AT + c] = Qg[idx];
        }
    }
    __syncthreads();

    unsigned qa[4][4];
    #pragma unroll
    for (int kk = 0; kk < 4; kk++)
        ldsm_x4(qa[kk][0], qa[kk][1], qa[kk][2], qa[kk][3],
                k_base + 2 * (r0 * AT + kk * 16 + xl));
    __syncthreads();

    float o[8][4];
    #pragma unroll
    for (int nf = 0; nf < 8; nf++)
        #pragma unroll
        for (int j = 0; j < 4; j++) o[nf][j] = 0.f;
    float m_lo = -1e30f, m_hi = -1e30f, l_lo = 0.f, l_hi = 0.f;

    const uint4* Kg0 = (const uint4*)(g_kh + (size_t)bh * (Ssz * Dsz));
    const uint4* Vg0 = (const uint4*)(g_vh + (size_t)bh * (Ssz * Dsz));

    for (int kb = 0; kb < Ssz / 256; kb++) {
        const uint4* Kg = Kg0 + kb * 2048;
        const uint4* Vg = Vg0 + kb * 2048;
        #pragma unroll
        for (int i = 0; i < 8; i++) {
            int idx = i * 256 + tid;
            int row = idx >> 3, c = (idx & 7) * 8;
            *(uint4*)&Ksm[row * AT + c] = Kg[idx];
            *(uint4*)&Vsm[row * AT + c] = Vg[idx];
        }
        __syncthreads();

        #pragma unroll
        for (int sub = 0; sub < 4; sub++) {
            const int so = sub * 64;

            float s[8][4];
            #pragma unroll
            for (int nf = 0; nf < 8; nf++)
                #pragma unroll
                for (int j = 0; j < 4; j++) s[nf][j] = 0.f;

            #pragma unroll
            for (int nfp = 0; nfp < 4; nfp++) {
                #pragma unroll
                for (int kk = 0; kk < 4; kk++) {
                    unsigned kb0, kb1, kb2, kb3;
                    ldsm_x4(kb0, kb1, kb2, kb3,
                            k_base + 2 * ((so + nfp * 16) * AT + kk * 16 + xl));
                    mma_f16(s[2 * nfp],     qa[kk], kb0, kb2);
                    mma_f16(s[2 * nfp + 1], qa[kk], kb1, kb3);
                }
            }

            float tmax_lo = -1e30f, tmax_hi = -1e30f;
            #pragma unroll
            for (int nf = 0; nf < 8; nf++) {
                tmax_lo = fmaxf(tmax_lo, fmaxf(s[nf][0], s[nf][1]));
                tmax_hi = fmaxf(tmax_hi, fmaxf(s[nf][2], s[nf][3]));
            }
            tmax_lo = fmaxf(tmax_lo, __shfl_xor_sync(0xffffffffu, tmax_lo, 1));
            tmax_lo = fmaxf(tmax_lo, __shfl_xor_sync(0xffffffffu, tmax_lo, 2));
            tmax_hi = fmaxf(tmax_hi, __shfl_xor_sync(0xffffffffu, tmax_hi, 1));
            tmax_hi = fmaxf(tmax_hi, __shfl_xor_sync(0xffffffffu, tmax_hi, 2));

            float mn_lo = fmaxf(m_lo, tmax_lo);
            float mn_hi = fmaxf(m_hi, tmax_hi);
            float a_lo = __expf(m_lo - mn_lo);
            float a_hi = __expf(m_hi - mn_hi);

            unsigned pa[4][4];
            float sum_lo = 0.f, sum_hi = 0.f;
            #pragma unroll
            for (int nf = 0; nf < 8; nf++) {
                float p0 = __expf(s[nf][0] - mn_lo);
                float p1 = __expf(s[nf][1] - mn_lo);
                float p2 = __expf(s[nf][2] - mn_hi);
                float p3 = __expf(s[nf][3] - mn_hi);
                sum_lo += p0 + p1;
                sum_hi += p2 + p3;
                const int kk = nf >> 1;
                const int half = (nf & 1) << 1;
                pa[kk][half]     = pack_h2(p0, p1);
                pa[kk][half + 1] = pack_h2(p2, p3);
                o[nf][0] *= a_lo; o[nf][1] *= a_lo;
                o[nf][2] *= a_hi; o[nf][3] *= a_hi;
            }
            sum_lo += __shfl_xor_sync(0xffffffffu, sum_lo, 1);
            sum_lo += __shfl_xor_sync(0xffffffffu, sum_lo, 2);
            sum_hi += __shfl_xor_sync(0xffffffffu, sum_hi, 1);
            sum_hi += __shfl_xor_sync(0xffffffffu, sum_hi, 2);
            l_lo = l_lo * a_lo + sum_lo;
            l_hi = l_hi * a_hi + sum_hi;
            m_lo = mn_lo; m_hi = mn_hi;

            #pragma unroll
            for (int kk = 0; kk < 4; kk++) {
                #pragma unroll
                for (int nfp = 0; nfp < 4; nfp++) {
                    unsigned v0, v1, v2, v3;
                    ldsm_x4t(v0, v1, v2, v3,
                             v_base + 2 * ((so + kk * 16 + (lane & 15)) * AT + nfp * 16 + (lane >> 4) * 8));
                    mma_f16(o[2 * nfp],     pa[kk], v0, v1);
                    mma_f16(o[2 * nfp + 1], pa[kk], v2, v3);
                }
            }
        }
        __syncthreads();
    }

    float inv_lo = 1.f / l_lo;
    float inv_hi = 1.f / l_hi;
    const int qrow_lo = blockIdx.x * 128 + r0 + g;
    __half* out_lo = g_ah + ((size_t)b * Ssz + qrow_lo) * Esz + h * Dsz;
    __half* out_hi = out_lo + 8 * Esz;
    #pragma unroll
    for (int nf = 0; nf < 8; nf++) {
        int col = nf * 8 + 2 * tg;
        *(__half2*)(out_lo + col) = __floats2half2_rn(o[nf][0] * inv_lo, o[nf][1] * inv_lo);
        *(__half2*)(out_hi + col) = __floats2half2_rn(o[nf][2] * inv_hi, o[nf][3] * inv_hi);
    }
}

// ---------------- launch ----------------
extern "C" void kernel_launch(void* const* d_in, const int* in_sizes, int n_in,
                              void* d_out, int out_size)
{
    const float* X  = (const float*)d_in[0];
    const float* Wq = (const float*)d_in[1];
    const float* bq = (const float*)d_in[2];
    const float* Wk = (const float*)d_in[3];
    const float* bk = (const float*)d_in[4];
    const float* Wv = (const float*)d_in[5];
    const float* bv = (const float*)d_in[6];
    const float* Wo = (const float*)d_in[7];
    const float* bo = (const float*)d_in[8];
    float* out = (float*)d_out;

    (void)cudaFuncSetAttribute(gemm_h, cudaFuncAttributeMaxDynamicSharedMemorySize, GSMEM);
    (void)cudaFuncSetAttribute(attn_kernel, cudaFuncAttributeMaxDynamicSharedMemorySize, ATTN_SMEM);

    // one-time fp16 conversions
    conv_x<<<(Msz * Esz) / (256 * 8), 256>>>(X);
    conv_wqkvT<<<3 * Esz, 128>>>(Wq, Wk, Wv);
    conv_woT<<<Esz, 128>>>(Wo);

    // QKV projection (fp16 mma + cp.async 3-stage, 256x128 tiles)
    gemm_h<<<dim3(18, 32), 512, GSMEM>>>(bq, bk, bv, nullptr, 0);

    // attention (Br=128, 256 keys per barrier round, register-resident P)
    attn_kernel<<<dim3(Ssz / 128, Bsz * Hsz), 256, ATTN_SMEM>>>();

    // output projection
    gemm_h<<<dim3(6, 32), 512, GSMEM>>>(bo, nullptr, nullptr, out, 1);
}